// round 6
// baseline (speedup 1.0000x reference)
#include <cuda_runtime.h>
#include <cuda_fp16.h>
#include <cstdint>

#define NN     20000
#define EE     640000
#define ETOT   660000      // EE + NN self loops
#define GG     64
#define FIN    128
#define FOUT   128
#define HEADS  4
#define HID    64
#define HC12   256         // HEADS*HID

// ---------------------------------------------------------------------------
// Scratch (device globals; zero-initialized at module load)
// ---------------------------------------------------------------------------
__device__ __half g_h16[(size_t)NN * HC12];   // h = x @ W (fp16, gather input)
__device__ float  g_bufB[(size_t)NN * HC12];  // aggregated out (fp32)
__device__ float  g_as[(size_t)NN * HEADS];
__device__ float  g_ad[(size_t)NN * HEADS];
__device__ float  g_gsum[GG * FOUT];
__device__ float  g_gcnt[GG];
__device__ int    g_deg[NN];                  // invariant: zero at call entry
__device__ int    g_off[NN + 1];
__device__ int    g_cur[NN];
__device__ int    g_csr_src[ETOT];

// ---------------------------------------------------------------------------
// TF32 helpers
// ---------------------------------------------------------------------------
__device__ __forceinline__ float to_tf32(float x) {
    uint32_t u;
    asm("cvt.rna.tf32.f32 %0, %1;" : "=r"(u) : "f"(x));
    return __uint_as_float(u);
}

__device__ __forceinline__ void mma_tf32(float* c, const uint32_t* a, const uint32_t* b) {
    asm volatile(
        "mma.sync.aligned.m16n8k8.row.col.f32.tf32.tf32.f32 "
        "{%0,%1,%2,%3}, {%4,%5,%6,%7}, {%8,%9}, {%0,%1,%2,%3};"
        : "+f"(c[0]), "+f"(c[1]), "+f"(c[2]), "+f"(c[3])
        : "r"(a[0]), "r"(a[1]), "r"(a[2]), "r"(a[3]), "r"(b[0]), "r"(b[1]));
}

// ---------------------------------------------------------------------------
// TF32 tensor-core GEMM: C[N,M] = A[N,K] * B[K,M], fp16 output.
// ---------------------------------------------------------------------------
__global__ __launch_bounds__(256) void gemm_tc_kernel(
    const float* __restrict__ A, const float* __restrict__ B,
    __half* __restrict__ C, int N, int K, int M)
{
    __shared__ float As[128][20];
    __shared__ float Bs[16][72];

    const int tid  = threadIdx.x;
    const int lane = tid & 31;
    const int warp = tid >> 5;
    const int wr   = (warp & 3) * 32;
    const int wc   = (warp >> 2) * 32;
    const int rowBase = blockIdx.y * 128;
    const int colBase = blockIdx.x * 64;
    const int g  = lane >> 2;
    const int tg = lane & 3;

    float acc[2][4][4];
#pragma unroll
    for (int i = 0; i < 2; i++)
#pragma unroll
        for (int j = 0; j < 4; j++)
#pragma unroll
            for (int k = 0; k < 4; k++) acc[i][j][k] = 0.f;

    for (int k0 = 0; k0 < K; k0 += 16) {
#pragma unroll
        for (int l = 0; l < 2; l++) {
            int i  = tid + l * 256;
            int r  = i >> 2;
            int c4 = (i & 3) * 4;
            int gr = rowBase + r;
            float4 v = make_float4(0.f, 0.f, 0.f, 0.f);
            if (gr < N) v = *reinterpret_cast<const float4*>(&A[(size_t)gr * K + k0 + c4]);
            v.x = to_tf32(v.x); v.y = to_tf32(v.y);
            v.z = to_tf32(v.z); v.w = to_tf32(v.w);
            *reinterpret_cast<float4*>(&As[r][c4]) = v;
        }
        {
            int r  = tid >> 4;
            int c4 = (tid & 15) * 4;
            float4 v = *reinterpret_cast<const float4*>(&B[(size_t)(k0 + r) * M + colBase + c4]);
            v.x = to_tf32(v.x); v.y = to_tf32(v.y);
            v.z = to_tf32(v.z); v.w = to_tf32(v.w);
            *reinterpret_cast<float4*>(&Bs[r][c4]) = v;
        }
        __syncthreads();

#pragma unroll
        for (int kk = 0; kk < 16; kk += 8) {
            uint32_t a[2][4], b[4][2];
#pragma unroll
            for (int i = 0; i < 2; i++) {
                int r0 = wr + i * 16 + g;
                a[i][0] = __float_as_uint(As[r0][kk + tg]);
                a[i][1] = __float_as_uint(As[r0 + 8][kk + tg]);
                a[i][2] = __float_as_uint(As[r0][kk + 4 + tg]);
                a[i][3] = __float_as_uint(As[r0 + 8][kk + 4 + tg]);
            }
#pragma unroll
            for (int j = 0; j < 4; j++) {
                int c0 = wc + j * 8 + g;
                b[j][0] = __float_as_uint(Bs[kk + tg][c0]);
                b[j][1] = __float_as_uint(Bs[kk + 4 + tg][c0]);
            }
#pragma unroll
            for (int i = 0; i < 2; i++)
#pragma unroll
                for (int j = 0; j < 4; j++)
                    mma_tf32(acc[i][j], a[i], b[j]);
        }
        __syncthreads();
    }

#pragma unroll
    for (int i = 0; i < 2; i++) {
        int r0 = rowBase + wr + i * 16 + g;
#pragma unroll
        for (int j = 0; j < 4; j++) {
            int c0 = colBase + wc + j * 8 + tg * 2;
            if (r0 < N) {
                __half2 v = __floats2half2_rn(acc[i][j][0], acc[i][j][1]);
                *reinterpret_cast<__half2*>(&C[(size_t)r0 * M + c0]) = v;
            }
            if (r0 + 8 < N) {
                __half2 v = __floats2half2_rn(acc[i][j][2], acc[i][j][3]);
                *reinterpret_cast<__half2*>(&C[(size_t)(r0 + 8) * M + c0]) = v;
            }
        }
    }
}

// ---------------------------------------------------------------------------
// CSR count (+ zero gsum/gcnt for the pool at end of call)
// ---------------------------------------------------------------------------
__global__ void csr_count_kernel(const int* __restrict__ ei, int* __restrict__ deg,
                                 float* __restrict__ gsum, float* __restrict__ gcnt)
{
    int t = blockIdx.x * blockDim.x + threadIdx.x;
    if (t < GG * FOUT) gsum[t] = 0.f;
    if (t < GG) gcnt[t] = 0.f;
    if (t >= ETOT) return;
    int d = (t < EE) ? ei[EE + t] : (t - EE);
    atomicAdd(&deg[d], 1);
}

// single block scan; re-zeroes deg after reading (keeps call-entry invariant)
__global__ __launch_bounds__(1024) void csr_scan_kernel(
    int* __restrict__ deg, int* __restrict__ off, int* __restrict__ cur)
{
    const int PER = 20;
    __shared__ int warpSums[32];
    int t    = threadIdx.x;
    int lane = t & 31, wid = t >> 5;
    int base = t * PER;

    int v[PER];
    int s = 0;
#pragma unroll
    for (int i = 0; i < PER; i++) {
        int idx = base + i;
        int x = (idx < NN) ? deg[idx] : 0;
        if (idx < NN) deg[idx] = 0;   // restore invariant
        v[i] = s;
        s += x;
    }
    int incl = s;
#pragma unroll
    for (int o = 1; o < 32; o <<= 1) {
        int u = __shfl_up_sync(0xffffffffu, incl, o);
        if (lane >= o) incl += u;
    }
    if (lane == 31) warpSums[wid] = incl;
    __syncthreads();
    if (wid == 0) {
        int ws = warpSums[lane];
#pragma unroll
        for (int o = 1; o < 32; o <<= 1) {
            int u = __shfl_up_sync(0xffffffffu, ws, o);
            if (lane >= o) ws += u;
        }
        warpSums[lane] = ws;
    }
    __syncthreads();
    int warpPrefix  = (wid == 0) ? 0 : warpSums[wid - 1];
    int threadExcl  = warpPrefix + incl - s;
#pragma unroll
    for (int i = 0; i < PER; i++) {
        int idx = base + i;
        if (idx < NN) {
            int e = threadExcl + v[i];
            off[idx] = e;
            cur[idx] = e;
        }
    }
    if (t == 0) off[NN] = ETOT;
}

__global__ void csr_scatter_kernel(const int* __restrict__ ei,
                                   int* __restrict__ cur, int* __restrict__ csr_src)
{
    int t = blockIdx.x * blockDim.x + threadIdx.x;
    if (t >= ETOT) return;
    int s, d;
    if (t < EE) { s = ei[t]; d = ei[EE + t]; }
    else        { s = t - EE; d = s; }
    int pos = atomicAdd(&cur[d], 1);
    csr_src[pos] = s;
}

// ---------------------------------------------------------------------------
// alpha_s / alpha_d from fp16 h: warp per (node, head)
// ---------------------------------------------------------------------------
__global__ void alpha_kernel(const __half* __restrict__ h,
                             const float* __restrict__ a_s,
                             const float* __restrict__ a_d,
                             float* __restrict__ outs, float* __restrict__ outd,
                             int H, int C)
{
    int gt   = blockIdx.x * blockDim.x + threadIdx.x;
    int wid  = gt >> 5;
    int lane = gt & 31;
    if (wid >= NN * H) return;
    int i  = wid / H;
    int hh = wid - i * H;
    const __half* hp = h + (size_t)i * H * C + hh * C;
    const float* asp = a_s + hh * C;
    const float* adp = a_d + hh * C;
    float ss = 0.f, sd = 0.f;
    for (int c = lane * 2; c < C; c += 64) {
        __half2 hv = *reinterpret_cast<const __half2*>(&hp[c]);
        float2 f = __half22float2(hv);
        ss += f.x * asp[c] + f.y * asp[c + 1];
        sd += f.x * adp[c] + f.y * adp[c + 1];
    }
#pragma unroll
    for (int o = 16; o; o >>= 1) {
        ss += __shfl_xor_sync(0xffffffffu, ss, o);
        sd += __shfl_xor_sync(0xffffffffu, sd, o);
    }
    if (lane == 0) { outs[wid] = ss; outd[wid] = sd; }
}

// ---------------------------------------------------------------------------
// GAT aggregation (H=4, C=64): TWO warps per dst node.
// Warp half=w&1 owns channels [half*128, half*128+128) = heads 2h, 2h+1.
// Lane l: 4 channels (uint2 of halves); lanes 0-15 head 2h, 16-31 head 2h+1.
// Software-pipelined edge loop (prefetch depth 1).
// ---------------------------------------------------------------------------
__global__ __launch_bounds__(256) void gat_gather4_kernel(
    const int* __restrict__ off, const int* __restrict__ csr_src,
    const __half* __restrict__ h,
    const float* __restrict__ as_, const float* __restrict__ ad_,
    const float* __restrict__ bias, float* __restrict__ out, int do_elu)
{
    int gt   = blockIdx.x * blockDim.x + threadIdx.x;
    int w    = gt >> 5;
    int lane = gt & 31;
    int d    = w >> 1;
    int half = w & 1;
    if (d >= NN) return;

    const float2* as2 = reinterpret_cast<const float2*>(as_);
    const uint2*  hb  = reinterpret_cast<const uint2*>(h);

    float2 adp = reinterpret_cast<const float2*>(ad_)[d * 2 + half];
    float adv = (lane < 16) ? adp.x : adp.y;

    float acc[4] = {0.f, 0.f, 0.f, 0.f};
    float den = 0.f;

    int a   = off[d];
    int end = off[d + 1];
    if (a < end) {
        int s = csr_src[a];
        float2 e2 = as2[s * 2 + half];
        uint2 hv = hb[(size_t)s * 64 + half * 32 + lane];
        for (; a < end; ) {
            a++;
            int sn = 0;
            float2 e2n = make_float2(0.f, 0.f);
            uint2 hvn = make_uint2(0u, 0u);
            if (a < end) {
                sn  = csr_src[a];
                e2n = as2[sn * 2 + half];
                hvn = hb[(size_t)sn * 64 + half * 32 + lane];
            }
            float e = ((lane < 16) ? e2.x : e2.y) + adv;
            e = e > 0.f ? e : 0.2f * e;
            float ex = __expf(e);
            float2 f0 = __half22float2(*reinterpret_cast<__half2*>(&hv.x));
            float2 f1 = __half22float2(*reinterpret_cast<__half2*>(&hv.y));
            acc[0] += ex * f0.x; acc[1] += ex * f0.y;
            acc[2] += ex * f1.x; acc[3] += ex * f1.y;
            den += ex;
            s = sn; e2 = e2n; hv = hvn;
        }
    }

    float r = 1.f / (den + 1e-16f);
    int cb = half * 128 + lane * 4;
    float4 b = *reinterpret_cast<const float4*>(&bias[cb]);
    float o0 = acc[0] * r + b.x;
    float o1 = acc[1] * r + b.y;
    float o2 = acc[2] * r + b.z;
    float o3 = acc[3] * r + b.w;
    if (do_elu) {
        o0 = o0 > 0.f ? o0 : expm1f(o0);
        o1 = o1 > 0.f ? o1 : expm1f(o1);
        o2 = o2 > 0.f ? o2 : expm1f(o2);
        o3 = o3 > 0.f ? o3 : expm1f(o3);
    }
    *reinterpret_cast<float4*>(&out[(size_t)d * HC12 + cb]) = make_float4(o0, o1, o2, o3);
}

// ---------------------------------------------------------------------------
// GAT aggregation (H=1, C=128): TWO warps per dst; lane owns 2 channels.
// Global mean pool fused into the epilogue.
// ---------------------------------------------------------------------------
__global__ __launch_bounds__(256) void gat_gather1_kernel(
    const int* __restrict__ off, const int* __restrict__ csr_src,
    const __half* __restrict__ h,
    const float* __restrict__ as_, const float* __restrict__ ad_,
    const float* __restrict__ bias, const int* __restrict__ batch,
    float* __restrict__ out, float* __restrict__ gsum, float* __restrict__ gcnt)
{
    int gt   = blockIdx.x * blockDim.x + threadIdx.x;
    int w    = gt >> 5;
    int lane = gt & 31;
    int d    = w >> 1;
    int half = w & 1;
    if (d >= NN) return;

    const __half2* hb = reinterpret_cast<const __half2*>(h);
    float adv = ad_[d];
    float acc0 = 0.f, acc1 = 0.f, den = 0.f;

    int a   = off[d];
    int end = off[d + 1];
    if (a < end) {
        int s = csr_src[a];
        float ea = as_[s];
        __half2 hv = hb[(size_t)s * 64 + half * 32 + lane];
        for (; a < end; ) {
            a++;
            int sn = 0;
            float ean = 0.f;
            __half2 hvn = __half2half2(__float2half(0.f));
            if (a < end) {
                sn  = csr_src[a];
                ean = as_[sn];
                hvn = hb[(size_t)sn * 64 + half * 32 + lane];
            }
            float e = ea + adv;
            e = e > 0.f ? e : 0.2f * e;
            float ex = __expf(e);
            float2 f = __half22float2(hv);
            acc0 += ex * f.x;
            acc1 += ex * f.y;
            den += ex;
            s = sn; ea = ean; hv = hvn;
        }
    }

    float r = 1.f / (den + 1e-16f);
    int c = half * 64 + lane * 2;
    float2 b = *reinterpret_cast<const float2*>(&bias[c]);
    float o0 = acc0 * r + b.x;
    float o1 = acc1 * r + b.y;
    *reinterpret_cast<float2*>(&out[(size_t)d * FOUT + c]) = make_float2(o0, o1);

    int g = batch[d];
    atomicAdd(&gsum[g * FOUT + c], o0);
    atomicAdd(&gsum[g * FOUT + c + 1], o1);
    if (lane == 0 && half == 0) atomicAdd(&gcnt[g], 1.f);
}

// ---------------------------------------------------------------------------
// Pool finalize
// ---------------------------------------------------------------------------
__global__ void pool_div_kernel(const float* __restrict__ gsum,
                                const float* __restrict__ cnt,
                                float* __restrict__ out)
{
    int t = blockIdx.x * blockDim.x + threadIdx.x;
    if (t >= GG * FOUT) return;
    out[t] = gsum[t] / fmaxf(cnt[t >> 7], 1.f);
}

// ---------------------------------------------------------------------------
// Launch
// ---------------------------------------------------------------------------
extern "C" void kernel_launch(void* const* d_in, const int* in_sizes, int n_in,
                              void* d_out, int out_size)
{
    const float* x   = (const float*)d_in[0];
    const int*   ei  = (const int*)d_in[1];
    const int*   bat = (const int*)d_in[2];
    const float* W1  = (const float*)d_in[3];
    const float* as1 = (const float*)d_in[4];
    const float* ad1 = (const float*)d_in[5];
    const float* b1  = (const float*)d_in[6];
    const float* W2  = (const float*)d_in[7];
    const float* as2 = (const float*)d_in[8];
    const float* ad2 = (const float*)d_in[9];
    const float* b2  = (const float*)d_in[10];
    const float* W3  = (const float*)d_in[11];
    const float* as3 = (const float*)d_in[12];
    const float* ad3 = (const float*)d_in[13];
    const float* b3  = (const float*)d_in[14];

    float* out     = (float*)d_out;
    float* out_emb = out;                 // [G, FOUT]
    float* out_h   = out + GG * FOUT;     // [N, FOUT]

    __half* h16;
    float *bufB, *as_, *ad_, *gsum, *gcnt;
    int *deg, *off, *cur, *csr_src;
    cudaGetSymbolAddress((void**)&h16,  g_h16);
    cudaGetSymbolAddress((void**)&bufB, g_bufB);
    cudaGetSymbolAddress((void**)&as_,  g_as);
    cudaGetSymbolAddress((void**)&ad_,  g_ad);
    cudaGetSymbolAddress((void**)&gsum, g_gsum);
    cudaGetSymbolAddress((void**)&gcnt, g_gcnt);
    cudaGetSymbolAddress((void**)&deg,  g_deg);
    cudaGetSymbolAddress((void**)&off,  g_off);
    cudaGetSymbolAddress((void**)&cur,  g_cur);
    cudaGetSymbolAddress((void**)&csr_src, g_csr_src);

    // --- CSR build (no memsets: deg invariant kept by scan kernel) ---
    csr_count_kernel<<<(ETOT + 255) / 256, 256>>>(ei, deg, gsum, gcnt);
    csr_scan_kernel<<<1, 1024>>>(deg, off, cur);
    csr_scatter_kernel<<<(ETOT + 255) / 256, 256>>>(ei, cur, csr_src);

    const int nby = (NN + 127) / 128;
    const int gatherGrid = (NN * 64 + 255) / 256;   // 2 warps per dst

    // --- Layer 1 ---
    gemm_tc_kernel<<<dim3(HC12 / 64, nby), 256>>>(x, W1, h16, NN, FIN, HC12);
    alpha_kernel<<<(NN * HEADS * 32 + 255) / 256, 256>>>(h16, as1, ad1, as_, ad_, HEADS, HID);
    gat_gather4_kernel<<<gatherGrid, 256>>>(off, csr_src, h16, as_, ad_, b1, bufB, 1);

    // --- Layer 2 ---
    gemm_tc_kernel<<<dim3(HC12 / 64, nby), 256>>>(bufB, W2, h16, NN, HC12, HC12);
    alpha_kernel<<<(NN * HEADS * 32 + 255) / 256, 256>>>(h16, as2, ad2, as_, ad_, HEADS, HID);
    gat_gather4_kernel<<<gatherGrid, 256>>>(off, csr_src, h16, as_, ad_, b2, bufB, 1);

    // --- Layer 3 (pool fused) ---
    gemm_tc_kernel<<<dim3(FOUT / 64, nby), 256>>>(bufB, W3, h16, NN, HC12, FOUT);
    alpha_kernel<<<(NN * 32 + 255) / 256, 256>>>(h16, as3, ad3, as_, ad_, 1, FOUT);
    gat_gather1_kernel<<<gatherGrid, 256>>>(off, csr_src, h16, as_, ad_, b3, bat,
                                            out_h, gsum, gcnt);

    pool_div_kernel<<<(GG * FOUT + 255) / 256, 256>>>(gsum, gcnt, out_emb);
}

// round 7
// speedup vs baseline: 1.1702x; 1.1702x over previous
#include <cuda_runtime.h>
#include <cuda_fp16.h>
#include <cstdint>

#define NN     20000
#define EE     640000
#define ETOT   660000      // EE + NN self loops
#define GG     64
#define FIN    128
#define FOUT   128
#define HEADS  4
#define HID    64
#define HC12   256         // HEADS*HID

// ---------------------------------------------------------------------------
// Scratch (device globals; zero-initialized at module load)
// ---------------------------------------------------------------------------
__device__ __half g_h16[(size_t)NN * HC12];   // h = x @ W (fp16, gather input)
__device__ float  g_bufB[(size_t)NN * HC12];  // aggregated out (fp32)
__device__ float  g_as[(size_t)NN * HEADS];
__device__ float  g_ad[(size_t)NN * HEADS];
__device__ float  g_gsum[GG * FOUT];
__device__ float  g_gcnt[GG];
__device__ int    g_deg[NN];                  // invariant: zero at call entry
__device__ int    g_off[NN + 1];
__device__ int    g_cur[NN];
__device__ int    g_csr_src[ETOT];

// ---------------------------------------------------------------------------
// TF32 helpers
// ---------------------------------------------------------------------------
__device__ __forceinline__ float to_tf32(float x) {
    uint32_t u;
    asm("cvt.rna.tf32.f32 %0, %1;" : "=r"(u) : "f"(x));
    return __uint_as_float(u);
}

__device__ __forceinline__ void mma_tf32(float* c, const uint32_t* a, const uint32_t* b) {
    asm volatile(
        "mma.sync.aligned.m16n8k8.row.col.f32.tf32.tf32.f32 "
        "{%0,%1,%2,%3}, {%4,%5,%6,%7}, {%8,%9}, {%0,%1,%2,%3};"
        : "+f"(c[0]), "+f"(c[1]), "+f"(c[2]), "+f"(c[3])
        : "r"(a[0]), "r"(a[1]), "r"(a[2]), "r"(a[3]), "r"(b[0]), "r"(b[1]));
}

// ---------------------------------------------------------------------------
// TF32 tensor-core GEMM: C[N,M] = A[N,K] * B[K,M], fp16 output.
// ---------------------------------------------------------------------------
__global__ __launch_bounds__(256) void gemm_tc_kernel(
    const float* __restrict__ A, const float* __restrict__ B,
    __half* __restrict__ C, int N, int K, int M)
{
    __shared__ float As[128][20];
    __shared__ float Bs[16][72];

    const int tid  = threadIdx.x;
    const int lane = tid & 31;
    const int warp = tid >> 5;
    const int wr   = (warp & 3) * 32;
    const int wc   = (warp >> 2) * 32;
    const int rowBase = blockIdx.y * 128;
    const int colBase = blockIdx.x * 64;
    const int g  = lane >> 2;
    const int tg = lane & 3;

    float acc[2][4][4];
#pragma unroll
    for (int i = 0; i < 2; i++)
#pragma unroll
        for (int j = 0; j < 4; j++)
#pragma unroll
            for (int k = 0; k < 4; k++) acc[i][j][k] = 0.f;

    for (int k0 = 0; k0 < K; k0 += 16) {
#pragma unroll
        for (int l = 0; l < 2; l++) {
            int i  = tid + l * 256;
            int r  = i >> 2;
            int c4 = (i & 3) * 4;
            int gr = rowBase + r;
            float4 v = make_float4(0.f, 0.f, 0.f, 0.f);
            if (gr < N) v = *reinterpret_cast<const float4*>(&A[(size_t)gr * K + k0 + c4]);
            v.x = to_tf32(v.x); v.y = to_tf32(v.y);
            v.z = to_tf32(v.z); v.w = to_tf32(v.w);
            *reinterpret_cast<float4*>(&As[r][c4]) = v;
        }
        {
            int r  = tid >> 4;
            int c4 = (tid & 15) * 4;
            float4 v = *reinterpret_cast<const float4*>(&B[(size_t)(k0 + r) * M + colBase + c4]);
            v.x = to_tf32(v.x); v.y = to_tf32(v.y);
            v.z = to_tf32(v.z); v.w = to_tf32(v.w);
            *reinterpret_cast<float4*>(&Bs[r][c4]) = v;
        }
        __syncthreads();

#pragma unroll
        for (int kk = 0; kk < 16; kk += 8) {
            uint32_t a[2][4], b[4][2];
#pragma unroll
            for (int i = 0; i < 2; i++) {
                int r0 = wr + i * 16 + g;
                a[i][0] = __float_as_uint(As[r0][kk + tg]);
                a[i][1] = __float_as_uint(As[r0 + 8][kk + tg]);
                a[i][2] = __float_as_uint(As[r0][kk + 4 + tg]);
                a[i][3] = __float_as_uint(As[r0 + 8][kk + 4 + tg]);
            }
#pragma unroll
            for (int j = 0; j < 4; j++) {
                int c0 = wc + j * 8 + g;
                b[j][0] = __float_as_uint(Bs[kk + tg][c0]);
                b[j][1] = __float_as_uint(Bs[kk + 4 + tg][c0]);
            }
#pragma unroll
            for (int i = 0; i < 2; i++)
#pragma unroll
                for (int j = 0; j < 4; j++)
                    mma_tf32(acc[i][j], a[i], b[j]);
        }
        __syncthreads();
    }

#pragma unroll
    for (int i = 0; i < 2; i++) {
        int r0 = rowBase + wr + i * 16 + g;
#pragma unroll
        for (int j = 0; j < 4; j++) {
            int c0 = colBase + wc + j * 8 + tg * 2;
            if (r0 < N) {
                __half2 v = __floats2half2_rn(acc[i][j][0], acc[i][j][1]);
                *reinterpret_cast<__half2*>(&C[(size_t)r0 * M + c0]) = v;
            }
            if (r0 + 8 < N) {
                __half2 v = __floats2half2_rn(acc[i][j][2], acc[i][j][3]);
                *reinterpret_cast<__half2*>(&C[(size_t)(r0 + 8) * M + c0]) = v;
            }
        }
    }
}

// ---------------------------------------------------------------------------
// CSR count (+ zero gsum/gcnt for the pool)
// ---------------------------------------------------------------------------
__global__ void csr_count_kernel(const int* __restrict__ ei, int* __restrict__ deg,
                                 float* __restrict__ gsum, float* __restrict__ gcnt)
{
    int t = blockIdx.x * blockDim.x + threadIdx.x;
    if (t < GG * FOUT) gsum[t] = 0.f;
    if (t < GG) gcnt[t] = 0.f;
    if (t >= ETOT) return;
    int d = (t < EE) ? ei[EE + t] : (t - EE);
    atomicAdd(&deg[d], 1);
}

// single block scan; re-zeroes deg after reading (keeps call-entry invariant)
__global__ __launch_bounds__(1024) void csr_scan_kernel(
    int* __restrict__ deg, int* __restrict__ off, int* __restrict__ cur)
{
    const int PER = 20;
    __shared__ int warpSums[32];
    int t    = threadIdx.x;
    int lane = t & 31, wid = t >> 5;
    int base = t * PER;

    int v[PER];
    int s = 0;
#pragma unroll
    for (int i = 0; i < PER; i++) {
        int idx = base + i;
        int x = (idx < NN) ? deg[idx] : 0;
        if (idx < NN) deg[idx] = 0;
        v[i] = s;
        s += x;
    }
    int incl = s;
#pragma unroll
    for (int o = 1; o < 32; o <<= 1) {
        int u = __shfl_up_sync(0xffffffffu, incl, o);
        if (lane >= o) incl += u;
    }
    if (lane == 31) warpSums[wid] = incl;
    __syncthreads();
    if (wid == 0) {
        int ws = warpSums[lane];
#pragma unroll
        for (int o = 1; o < 32; o <<= 1) {
            int u = __shfl_up_sync(0xffffffffu, ws, o);
            if (lane >= o) ws += u;
        }
        warpSums[lane] = ws;
    }
    __syncthreads();
    int warpPrefix  = (wid == 0) ? 0 : warpSums[wid - 1];
    int threadExcl  = warpPrefix + incl - s;
#pragma unroll
    for (int i = 0; i < PER; i++) {
        int idx = base + i;
        if (idx < NN) {
            int e = threadExcl + v[i];
            off[idx] = e;
            cur[idx] = e;
        }
    }
    if (t == 0) off[NN] = ETOT;
}

__global__ void csr_scatter_kernel(const int* __restrict__ ei,
                                   int* __restrict__ cur, int* __restrict__ csr_src)
{
    int t = blockIdx.x * blockDim.x + threadIdx.x;
    if (t >= ETOT) return;
    int s, d;
    if (t < EE) { s = ei[t]; d = ei[EE + t]; }
    else        { s = t - EE; d = s; }
    int pos = atomicAdd(&cur[d], 1);
    csr_src[pos] = s;
}

// ---------------------------------------------------------------------------
// alpha_s / alpha_d from fp16 h: warp per (node, head)
// ---------------------------------------------------------------------------
__global__ void alpha_kernel(const __half* __restrict__ h,
                             const float* __restrict__ a_s,
                             const float* __restrict__ a_d,
                             float* __restrict__ outs, float* __restrict__ outd,
                             int H, int C)
{
    int gt   = blockIdx.x * blockDim.x + threadIdx.x;
    int wid  = gt >> 5;
    int lane = gt & 31;
    if (wid >= NN * H) return;
    int i  = wid / H;
    int hh = wid - i * H;
    const __half* hp = h + (size_t)i * H * C + hh * C;
    const float* asp = a_s + hh * C;
    const float* adp = a_d + hh * C;
    float ss = 0.f, sd = 0.f;
    for (int c = lane * 2; c < C; c += 64) {
        __half2 hv = *reinterpret_cast<const __half2*>(&hp[c]);
        float2 f = __half22float2(hv);
        ss += f.x * asp[c] + f.y * asp[c + 1];
        sd += f.x * adp[c] + f.y * adp[c + 1];
    }
#pragma unroll
    for (int o = 16; o; o >>= 1) {
        ss += __shfl_xor_sync(0xffffffffu, ss, o);
        sd += __shfl_xor_sync(0xffffffffu, sd, o);
    }
    if (lane == 0) { outs[wid] = ss; outd[wid] = sd; }
}

// ---------------------------------------------------------------------------
// GAT aggregation (H=4, C=64), fp16 h: ONE warp per dst node.
// Lane l owns 8 contiguous channels (uint4); head = l>>3.
// Per-edge alpha via direct scalar load as_[s*4+head] (broadcast line).
// Unroll-2 over edges for MLP.
// ---------------------------------------------------------------------------
__global__ __launch_bounds__(256) void gat_gather4_kernel(
    const int* __restrict__ off, const int* __restrict__ csr_src,
    const __half* __restrict__ h,
    const float* __restrict__ as_, const float* __restrict__ ad_,
    const float* __restrict__ bias, float* __restrict__ out, int do_elu)
{
    int gt   = blockIdx.x * blockDim.x + threadIdx.x;
    int d    = gt >> 5;
    int lane = gt & 31;
    if (d >= NN) return;

    const int head = lane >> 3;
    const uint4* hb = reinterpret_cast<const uint4*>(h);
    float adv = ad_[d * 4 + head];

    float acc[8];
#pragma unroll
    for (int k = 0; k < 8; k++) acc[k] = 0.f;
    float den = 0.f;

    int a   = off[d];
    int end = off[d + 1];
    for (; a + 1 < end; a += 2) {
        int s0 = csr_src[a];
        int s1 = csr_src[a + 1];
        float e0 = as_[s0 * 4 + head] + adv;
        float e1 = as_[s1 * 4 + head] + adv;
        uint4 v0 = hb[(size_t)s0 * 32 + lane];
        uint4 v1 = hb[(size_t)s1 * 32 + lane];
        e0 = e0 > 0.f ? e0 : 0.2f * e0;
        e1 = e1 > 0.f ? e1 : 0.2f * e1;
        float x0 = __expf(e0);
        float x1 = __expf(e1);
        {
            float2 f0 = __half22float2(*reinterpret_cast<__half2*>(&v0.x));
            float2 f1 = __half22float2(*reinterpret_cast<__half2*>(&v0.y));
            float2 f2 = __half22float2(*reinterpret_cast<__half2*>(&v0.z));
            float2 f3 = __half22float2(*reinterpret_cast<__half2*>(&v0.w));
            acc[0] += x0 * f0.x; acc[1] += x0 * f0.y;
            acc[2] += x0 * f1.x; acc[3] += x0 * f1.y;
            acc[4] += x0 * f2.x; acc[5] += x0 * f2.y;
            acc[6] += x0 * f3.x; acc[7] += x0 * f3.y;
        }
        {
            float2 f0 = __half22float2(*reinterpret_cast<__half2*>(&v1.x));
            float2 f1 = __half22float2(*reinterpret_cast<__half2*>(&v1.y));
            float2 f2 = __half22float2(*reinterpret_cast<__half2*>(&v1.z));
            float2 f3 = __half22float2(*reinterpret_cast<__half2*>(&v1.w));
            acc[0] += x1 * f0.x; acc[1] += x1 * f0.y;
            acc[2] += x1 * f1.x; acc[3] += x1 * f1.y;
            acc[4] += x1 * f2.x; acc[5] += x1 * f2.y;
            acc[6] += x1 * f3.x; acc[7] += x1 * f3.y;
        }
        den += x0 + x1;
    }
    if (a < end) {
        int s = csr_src[a];
        float e = as_[s * 4 + head] + adv;
        uint4 v = hb[(size_t)s * 32 + lane];
        e = e > 0.f ? e : 0.2f * e;
        float ex = __expf(e);
        float2 f0 = __half22float2(*reinterpret_cast<__half2*>(&v.x));
        float2 f1 = __half22float2(*reinterpret_cast<__half2*>(&v.y));
        float2 f2 = __half22float2(*reinterpret_cast<__half2*>(&v.z));
        float2 f3 = __half22float2(*reinterpret_cast<__half2*>(&v.w));
        acc[0] += ex * f0.x; acc[1] += ex * f0.y;
        acc[2] += ex * f1.x; acc[3] += ex * f1.y;
        acc[4] += ex * f2.x; acc[5] += ex * f2.y;
        acc[6] += ex * f3.x; acc[7] += ex * f3.y;
        den += ex;
    }

    float r = 1.f / (den + 1e-16f);
    float4 b0 = *reinterpret_cast<const float4*>(&bias[lane * 8]);
    float4 b1 = *reinterpret_cast<const float4*>(&bias[lane * 8 + 4]);
    float o[8];
    o[0] = acc[0] * r + b0.x; o[1] = acc[1] * r + b0.y;
    o[2] = acc[2] * r + b0.z; o[3] = acc[3] * r + b0.w;
    o[4] = acc[4] * r + b1.x; o[5] = acc[5] * r + b1.y;
    o[6] = acc[6] * r + b1.z; o[7] = acc[7] * r + b1.w;
    if (do_elu) {
#pragma unroll
        for (int k = 0; k < 8; k++) o[k] = o[k] > 0.f ? o[k] : expm1f(o[k]);
    }
    float4* op = reinterpret_cast<float4*>(out + (size_t)d * HC12 + lane * 8);
    op[0] = make_float4(o[0], o[1], o[2], o[3]);
    op[1] = make_float4(o[4], o[5], o[6], o[7]);
}

// ---------------------------------------------------------------------------
// GAT aggregation (H=1, C=128), fp16 h: ONE warp per dst; lane owns 4 chans.
// ---------------------------------------------------------------------------
__global__ __launch_bounds__(256) void gat_gather1_kernel(
    const int* __restrict__ off, const int* __restrict__ csr_src,
    const __half* __restrict__ h,
    const float* __restrict__ as_, const float* __restrict__ ad_,
    const float* __restrict__ bias, float* __restrict__ out)
{
    int gt   = blockIdx.x * blockDim.x + threadIdx.x;
    int d    = gt >> 5;
    int lane = gt & 31;
    if (d >= NN) return;

    const uint2* hb = reinterpret_cast<const uint2*>(h);
    float adv = ad_[d];
    float acc[4] = {0.f, 0.f, 0.f, 0.f};
    float den = 0.f;

    int a   = off[d];
    int end = off[d + 1];
    for (; a + 1 < end; a += 2) {
        int s0 = csr_src[a];
        int s1 = csr_src[a + 1];
        float e0 = as_[s0] + adv;
        float e1 = as_[s1] + adv;
        uint2 v0 = hb[(size_t)s0 * 32 + lane];
        uint2 v1 = hb[(size_t)s1 * 32 + lane];
        e0 = e0 > 0.f ? e0 : 0.2f * e0;
        e1 = e1 > 0.f ? e1 : 0.2f * e1;
        float x0 = __expf(e0);
        float x1 = __expf(e1);
        {
            float2 f0 = __half22float2(*reinterpret_cast<__half2*>(&v0.x));
            float2 f1 = __half22float2(*reinterpret_cast<__half2*>(&v0.y));
            acc[0] += x0 * f0.x; acc[1] += x0 * f0.y;
            acc[2] += x0 * f1.x; acc[3] += x0 * f1.y;
        }
        {
            float2 f0 = __half22float2(*reinterpret_cast<__half2*>(&v1.x));
            float2 f1 = __half22float2(*reinterpret_cast<__half2*>(&v1.y));
            acc[0] += x1 * f0.x; acc[1] += x1 * f0.y;
            acc[2] += x1 * f1.x; acc[3] += x1 * f1.y;
        }
        den += x0 + x1;
    }
    if (a < end) {
        int s = csr_src[a];
        float e = as_[s] + adv;
        uint2 v = hb[(size_t)s * 32 + lane];
        e = e > 0.f ? e : 0.2f * e;
        float ex = __expf(e);
        float2 f0 = __half22float2(*reinterpret_cast<__half2*>(&v.x));
        float2 f1 = __half22float2(*reinterpret_cast<__half2*>(&v.y));
        acc[0] += ex * f0.x; acc[1] += ex * f0.y;
        acc[2] += ex * f1.x; acc[3] += ex * f1.y;
        den += ex;
    }

    float r = 1.f / (den + 1e-16f);
    float4 b = *reinterpret_cast<const float4*>(&bias[lane * 4]);
    float4 o;
    o.x = acc[0] * r + b.x; o.y = acc[1] * r + b.y;
    o.z = acc[2] * r + b.z; o.w = acc[3] * r + b.w;
    reinterpret_cast<float4*>(out + (size_t)d * FOUT)[lane] = o;
}

// ---------------------------------------------------------------------------
// Global mean pool
// ---------------------------------------------------------------------------
__global__ void pool_cnt_kernel(const int* __restrict__ batch, float* __restrict__ cnt)
{
    int t = blockIdx.x * blockDim.x + threadIdx.x;
    if (t >= NN) return;
    atomicAdd(&cnt[batch[t]], 1.f);
}

__global__ void pool_sum_kernel(const float* __restrict__ h,
                                const int* __restrict__ batch,
                                float* __restrict__ gsum)
{
    int t = blockIdx.x * blockDim.x + threadIdx.x;
    if (t >= NN * FOUT) return;
    int n = t >> 7;
    int c = t & 127;
    atomicAdd(&gsum[batch[n] * FOUT + c], h[t]);
}

__global__ void pool_div_kernel(const float* __restrict__ gsum,
                                const float* __restrict__ cnt,
                                float* __restrict__ out)
{
    int t = blockIdx.x * blockDim.x + threadIdx.x;
    if (t >= GG * FOUT) return;
    out[t] = gsum[t] / fmaxf(cnt[t >> 7], 1.f);
}

// ---------------------------------------------------------------------------
// Launch
// ---------------------------------------------------------------------------
extern "C" void kernel_launch(void* const* d_in, const int* in_sizes, int n_in,
                              void* d_out, int out_size)
{
    const float* x   = (const float*)d_in[0];
    const int*   ei  = (const int*)d_in[1];
    const int*   bat = (const int*)d_in[2];
    const float* W1  = (const float*)d_in[3];
    const float* as1 = (const float*)d_in[4];
    const float* ad1 = (const float*)d_in[5];
    const float* b1  = (const float*)d_in[6];
    const float* W2  = (const float*)d_in[7];
    const float* as2 = (const float*)d_in[8];
    const float* ad2 = (const float*)d_in[9];
    const float* b2  = (const float*)d_in[10];
    const float* W3  = (const float*)d_in[11];
    const float* as3 = (const float*)d_in[12];
    const float* ad3 = (const float*)d_in[13];
    const float* b3  = (const float*)d_in[14];

    float* out     = (float*)d_out;
    float* out_emb = out;                 // [G, FOUT]
    float* out_h   = out + GG * FOUT;     // [N, FOUT]

    __half* h16;
    float *bufB, *as_, *ad_, *gsum, *gcnt;
    int *deg, *off, *cur, *csr_src;
    cudaGetSymbolAddress((void**)&h16,  g_h16);
    cudaGetSymbolAddress((void**)&bufB, g_bufB);
    cudaGetSymbolAddress((void**)&as_,  g_as);
    cudaGetSymbolAddress((void**)&ad_,  g_ad);
    cudaGetSymbolAddress((void**)&gsum, g_gsum);
    cudaGetSymbolAddress((void**)&gcnt, g_gcnt);
    cudaGetSymbolAddress((void**)&deg,  g_deg);
    cudaGetSymbolAddress((void**)&off,  g_off);
    cudaGetSymbolAddress((void**)&cur,  g_cur);
    cudaGetSymbolAddress((void**)&csr_src, g_csr_src);

    // --- CSR build (no memsets) ---
    csr_count_kernel<<<(ETOT + 255) / 256, 256>>>(ei, deg, gsum, gcnt);
    csr_scan_kernel<<<1, 1024>>>(deg, off, cur);
    csr_scatter_kernel<<<(ETOT + 255) / 256, 256>>>(ei, cur, csr_src);

    const int nby = (NN + 127) / 128;
    const int gatherGrid = (NN * 32 + 255) / 256;   // 1 warp per dst

    // --- Layer 1 ---
    gemm_tc_kernel<<<dim3(HC12 / 64, nby), 256>>>(x, W1, h16, NN, FIN, HC12);
    alpha_kernel<<<(NN * HEADS * 32 + 255) / 256, 256>>>(h16, as1, ad1, as_, ad_, HEADS, HID);
    gat_gather4_kernel<<<gatherGrid, 256>>>(off, csr_src, h16, as_, ad_, b1, bufB, 1);

    // --- Layer 2 ---
    gemm_tc_kernel<<<dim3(HC12 / 64, nby), 256>>>(bufB, W2, h16, NN, HC12, HC12);
    alpha_kernel<<<(NN * HEADS * 32 + 255) / 256, 256>>>(h16, as2, ad2, as_, ad_, HEADS, HID);
    gat_gather4_kernel<<<gatherGrid, 256>>>(off, csr_src, h16, as_, ad_, b2, bufB, 1);

    // --- Layer 3 ---
    gemm_tc_kernel<<<dim3(FOUT / 64, nby), 256>>>(bufB, W3, h16, NN, HC12, FOUT);
    alpha_kernel<<<(NN * 32 + 255) / 256, 256>>>(h16, as3, ad3, as_, ad_, 1, FOUT);
    gat_gather1_kernel<<<gatherGrid, 256>>>(off, csr_src, h16, as_, ad_, b3, out_h);

    // --- Global mean pool ---
    pool_cnt_kernel<<<(NN + 255) / 256, 256>>>(bat, gcnt);
    pool_sum_kernel<<<(NN * FOUT + 255) / 256, 256>>>(out_h, bat, gsum);
    pool_div_kernel<<<(GG * FOUT + 255) / 256, 256>>>(gsum, gcnt, out_emb);
}

// round 8
// speedup vs baseline: 1.3178x; 1.1261x over previous
#include <cuda_runtime.h>
#include <cuda_fp16.h>
#include <cstdint>

#define NN     20000
#define EE     640000
#define ETOT   660000      // EE + NN self loops
#define GG     64
#define FIN    128
#define FOUT   128
#define HEADS  4
#define HID    64
#define HC12   256         // HEADS*HID

// ---------------------------------------------------------------------------
// Scratch (device globals; zero-initialized at module load)
// ---------------------------------------------------------------------------
__device__ __half g_h16[(size_t)NN * HC12];   // h = x @ W (fp16, gather input)
__device__ float  g_bufB[(size_t)NN * HC12];  // aggregated out (fp32, tf32-rounded)
__device__ float  g_xtf[(size_t)NN * FIN];    // x pre-rounded to tf32
__device__ float  g_wtf[131072];              // W1|W2|W3 pre-rounded to tf32
__device__ float  g_asA[(size_t)NN * HEADS];
__device__ float  g_adA[(size_t)NN * HEADS];
__device__ float  g_asB[(size_t)NN * HEADS];
__device__ float  g_adB[(size_t)NN * HEADS];
__device__ float  g_gsum[GG * FOUT];
__device__ float  g_gcnt[GG];
__device__ int    g_deg[NN];                  // invariant: zero at call entry
__device__ int    g_off[NN + 1];
__device__ int    g_cur[NN];
__device__ int    g_csr_src[ETOT];

// ---------------------------------------------------------------------------
// TF32 helpers
// ---------------------------------------------------------------------------
__device__ __forceinline__ float to_tf32(float x) {
    uint32_t u;
    asm("cvt.rna.tf32.f32 %0, %1;" : "=r"(u) : "f"(x));
    return __uint_as_float(u);
}

__device__ __forceinline__ void mma_tf32(float* c, const uint32_t* a, const uint32_t* b) {
    asm volatile(
        "mma.sync.aligned.m16n8k8.row.col.f32.tf32.tf32.f32 "
        "{%0,%1,%2,%3}, {%4,%5,%6,%7}, {%8,%9}, {%0,%1,%2,%3};"
        : "+f"(c[0]), "+f"(c[1]), "+f"(c[2]), "+f"(c[3])
        : "r"(a[0]), "r"(a[1]), "r"(a[2]), "r"(a[3]), "r"(b[0]), "r"(b[1]));
}

// ---------------------------------------------------------------------------
// Pre-round inputs to tf32 (so GEMM can cp.async raw bytes)
// ---------------------------------------------------------------------------
__global__ void cvt_kernel(const float* __restrict__ x, float* __restrict__ xtf,
                           const float* __restrict__ W1, const float* __restrict__ W2,
                           const float* __restrict__ W3, float* __restrict__ wtf)
{
    int t = blockIdx.x * blockDim.x + threadIdx.x;
    if (t < NN * FIN) xtf[t] = to_tf32(x[t]);
    if (t < 32768)        wtf[t] = to_tf32(W1[t]);
    else if (t < 98304)   wtf[t] = to_tf32(W2[t - 32768]);
    else if (t < 131072)  wtf[t] = to_tf32(W3[t - 98304]);
}

// ---------------------------------------------------------------------------
// Double-buffered TF32 GEMM with fused alpha epilogue.
// C16[N,M] = A[N,K]*B[K,M] (fp16 out); also:
//   outs[row*H + colBase/Cdim] += sum_cols acc*avs[col]  (atomic), same for outd.
// BM=128, BN=64, BK=16; 8 warps x (32x32); mma m16n8k8; cp.async 2 stages.
// ---------------------------------------------------------------------------
__global__ __launch_bounds__(256) void gemm_tc_kernel(
    const float* __restrict__ A, const float* __restrict__ B,
    __half* __restrict__ C, int N, int K, int M,
    const float* __restrict__ avs, const float* __restrict__ avd,
    float* __restrict__ outs, float* __restrict__ outd, int H, int Cdim)
{
    __shared__ float As[2][128][20];  // stride 20 -> conflict-free frag loads
    __shared__ float Bs[2][16][72];   // stride 72 -> conflict-free frag loads

    const int tid  = threadIdx.x;
    const int lane = tid & 31;
    const int warp = tid >> 5;
    const int wr   = (warp & 3) * 32;
    const int wc   = (warp >> 2) * 32;
    const int rowBase = blockIdx.y * 128;
    const int colBase = blockIdx.x * 64;
    const int g  = lane >> 2;
    const int tg = lane & 3;

    const int ar0 = tid >> 2;
    const int ac4 = (tid & 3) * 4;
    const int br  = tid >> 4;
    const int bc4 = (tid & 15) * 4;

    float acc[2][4][4];
#pragma unroll
    for (int i = 0; i < 2; i++)
#pragma unroll
        for (int j = 0; j < 4; j++)
#pragma unroll
            for (int k = 0; k < 4; k++) acc[i][j][k] = 0.f;

    auto stage = [&](int k0, int st) {
#pragma unroll
        for (int l = 0; l < 2; l++) {
            int r  = ar0 + l * 64;
            int gr = rowBase + r;
            uint32_t dst = (uint32_t)__cvta_generic_to_shared(&As[st][r][ac4]);
            const float* src = (gr < N) ? &A[(size_t)gr * K + k0 + ac4] : A;
            int sz = (gr < N) ? 16 : 0;
            asm volatile("cp.async.cg.shared.global [%0], [%1], 16, %2;"
                         :: "r"(dst), "l"(src), "r"(sz));
        }
        {
            uint32_t dst = (uint32_t)__cvta_generic_to_shared(&Bs[st][br][bc4]);
            const float* src = &B[(size_t)(k0 + br) * M + colBase + bc4];
            asm volatile("cp.async.cg.shared.global [%0], [%1], 16;"
                         :: "r"(dst), "l"(src));
        }
        asm volatile("cp.async.commit_group;");
    };

    const int T = K >> 4;
    stage(0, 0);
    for (int it = 0; it < T; it++) {
        if (it + 1 < T) {
            stage((it + 1) << 4, (it + 1) & 1);
            asm volatile("cp.async.wait_group 1;");
        } else {
            asm volatile("cp.async.wait_group 0;");
        }
        __syncthreads();
        int st = it & 1;
#pragma unroll
        for (int kk = 0; kk < 16; kk += 8) {
            uint32_t a[2][4], b[4][2];
#pragma unroll
            for (int i = 0; i < 2; i++) {
                int r0 = wr + i * 16 + g;
                a[i][0] = __float_as_uint(As[st][r0][kk + tg]);
                a[i][1] = __float_as_uint(As[st][r0 + 8][kk + tg]);
                a[i][2] = __float_as_uint(As[st][r0][kk + 4 + tg]);
                a[i][3] = __float_as_uint(As[st][r0 + 8][kk + 4 + tg]);
            }
#pragma unroll
            for (int j = 0; j < 4; j++) {
                int c0 = wc + j * 8 + g;
                b[j][0] = __float_as_uint(Bs[st][kk + tg][c0]);
                b[j][1] = __float_as_uint(Bs[st][kk + 4 + tg][c0]);
            }
#pragma unroll
            for (int i = 0; i < 2; i++)
#pragma unroll
                for (int j = 0; j < 4; j++)
                    mma_tf32(acc[i][j], a[i], b[j]);
        }
        __syncthreads();
    }

    // ---- writeback fp16 C ----
#pragma unroll
    for (int i = 0; i < 2; i++) {
        int r0 = rowBase + wr + i * 16 + g;
#pragma unroll
        for (int j = 0; j < 4; j++) {
            int c0 = colBase + wc + j * 8 + tg * 2;
            if (r0 < N) {
                __half2 v = __floats2half2_rn(acc[i][j][0], acc[i][j][1]);
                *reinterpret_cast<__half2*>(&C[(size_t)r0 * M + c0]) = v;
            }
            if (r0 + 8 < N) {
                __half2 v = __floats2half2_rn(acc[i][j][2], acc[i][j][3]);
                *reinterpret_cast<__half2*>(&C[(size_t)(r0 + 8) * M + c0]) = v;
            }
        }
    }

    // ---- fused alpha partials ----
    const int head = colBase / Cdim;
    float ps[2][2], pd[2][2];
#pragma unroll
    for (int i = 0; i < 2; i++) { ps[i][0]=ps[i][1]=pd[i][0]=pd[i][1]=0.f; }
#pragma unroll
    for (int j = 0; j < 4; j++) {
        int c0 = colBase + wc + j * 8 + tg * 2;
        float s0 = avs[c0], s1 = avs[c0 + 1];
        float d0 = avd[c0], d1 = avd[c0 + 1];
#pragma unroll
        for (int i = 0; i < 2; i++) {
            ps[i][0] += acc[i][j][0] * s0 + acc[i][j][1] * s1;
            pd[i][0] += acc[i][j][0] * d0 + acc[i][j][1] * d1;
            ps[i][1] += acc[i][j][2] * s0 + acc[i][j][3] * s1;
            pd[i][1] += acc[i][j][2] * d0 + acc[i][j][3] * d1;
        }
    }
#pragma unroll
    for (int o = 1; o < 4; o <<= 1) {
#pragma unroll
        for (int i = 0; i < 2; i++) {
#pragma unroll
            for (int sr = 0; sr < 2; sr++) {
                ps[i][sr] += __shfl_xor_sync(0xffffffffu, ps[i][sr], o);
                pd[i][sr] += __shfl_xor_sync(0xffffffffu, pd[i][sr], o);
            }
        }
    }
    if (tg == 0) {
#pragma unroll
        for (int i = 0; i < 2; i++) {
            int ra = rowBase + wr + i * 16 + g;
            if (ra < N) {
                atomicAdd(&outs[ra * H + head], ps[i][0]);
                atomicAdd(&outd[ra * H + head], pd[i][0]);
            }
            int rb = ra + 8;
            if (rb < N) {
                atomicAdd(&outs[rb * H + head], ps[i][1]);
                atomicAdd(&outd[rb * H + head], pd[i][1]);
            }
        }
    }
}

// ---------------------------------------------------------------------------
// CSR count (+ zero alpha buffers, gsum/gcnt)
// ---------------------------------------------------------------------------
__global__ void csr_count_kernel(const int* __restrict__ ei, int* __restrict__ deg,
                                 float* __restrict__ asA, float* __restrict__ adA,
                                 float* __restrict__ asB, float* __restrict__ adB,
                                 float* __restrict__ gsum, float* __restrict__ gcnt)
{
    int t = blockIdx.x * blockDim.x + threadIdx.x;
    if (t < NN * HEADS) { asA[t] = 0.f; adA[t] = 0.f; asB[t] = 0.f; adB[t] = 0.f; }
    if (t < GG * FOUT) gsum[t] = 0.f;
    if (t < GG) gcnt[t] = 0.f;
    if (t >= ETOT) return;
    int d = (t < EE) ? ei[EE + t] : (t - EE);
    atomicAdd(&deg[d], 1);
}

// single block scan; re-zeroes deg after reading (keeps call-entry invariant)
__global__ __launch_bounds__(1024) void csr_scan_kernel(
    int* __restrict__ deg, int* __restrict__ off, int* __restrict__ cur)
{
    const int PER = 20;
    __shared__ int warpSums[32];
    int t    = threadIdx.x;
    int lane = t & 31, wid = t >> 5;
    int base = t * PER;

    int v[PER];
    int s = 0;
#pragma unroll
    for (int i = 0; i < PER; i++) {
        int idx = base + i;
        int x = (idx < NN) ? deg[idx] : 0;
        if (idx < NN) deg[idx] = 0;
        v[i] = s;
        s += x;
    }
    int incl = s;
#pragma unroll
    for (int o = 1; o < 32; o <<= 1) {
        int u = __shfl_up_sync(0xffffffffu, incl, o);
        if (lane >= o) incl += u;
    }
    if (lane == 31) warpSums[wid] = incl;
    __syncthreads();
    if (wid == 0) {
        int ws = warpSums[lane];
#pragma unroll
        for (int o = 1; o < 32; o <<= 1) {
            int u = __shfl_up_sync(0xffffffffu, ws, o);
            if (lane >= o) ws += u;
        }
        warpSums[lane] = ws;
    }
    __syncthreads();
    int warpPrefix  = (wid == 0) ? 0 : warpSums[wid - 1];
    int threadExcl  = warpPrefix + incl - s;
#pragma unroll
    for (int i = 0; i < PER; i++) {
        int idx = base + i;
        if (idx < NN) {
            int e = threadExcl + v[i];
            off[idx] = e;
            cur[idx] = e;
        }
    }
    if (t == 0) off[NN] = ETOT;
}

__global__ void csr_scatter_kernel(const int* __restrict__ ei,
                                   int* __restrict__ cur, int* __restrict__ csr_src)
{
    int t = blockIdx.x * blockDim.x + threadIdx.x;
    if (t >= ETOT) return;
    int s, d;
    if (t < EE) { s = ei[t]; d = ei[EE + t]; }
    else        { s = t - EE; d = s; }
    int pos = atomicAdd(&cur[d], 1);
    csr_src[pos] = s;
}

// ---------------------------------------------------------------------------
// GAT aggregation (H=4, C=64), fp16 h: ONE warp per dst node.
// Lane l owns 8 contiguous channels (uint4); head = l>>3. Unroll-2 edges.
// Output tf32-rounded (feeds next GEMM via raw cp.async).
// Optional zero-tail clears alpha buffers for a later layer.
// ---------------------------------------------------------------------------
__global__ __launch_bounds__(256) void gat_gather4_kernel(
    const int* __restrict__ off, const int* __restrict__ csr_src,
    const __half* __restrict__ h,
    const float* __restrict__ as_, const float* __restrict__ ad_,
    const float* __restrict__ bias, float* __restrict__ out,
    float* __restrict__ za, float* __restrict__ zd)
{
    int gt   = blockIdx.x * blockDim.x + threadIdx.x;
    if (za != nullptr && gt < NN * HEADS) { za[gt] = 0.f; zd[gt] = 0.f; }
    int d    = gt >> 5;
    int lane = gt & 31;
    if (d >= NN) return;

    const int head = lane >> 3;
    const uint4* hb = reinterpret_cast<const uint4*>(h);
    float adv = ad_[d * 4 + head];

    float acc[8];
#pragma unroll
    for (int k = 0; k < 8; k++) acc[k] = 0.f;
    float den = 0.f;

    int a   = off[d];
    int end = off[d + 1];
    for (; a + 1 < end; a += 2) {
        int s0 = csr_src[a];
        int s1 = csr_src[a + 1];
        float e0 = as_[s0 * 4 + head] + adv;
        float e1 = as_[s1 * 4 + head] + adv;
        uint4 v0 = hb[(size_t)s0 * 32 + lane];
        uint4 v1 = hb[(size_t)s1 * 32 + lane];
        e0 = e0 > 0.f ? e0 : 0.2f * e0;
        e1 = e1 > 0.f ? e1 : 0.2f * e1;
        float x0 = __expf(e0);
        float x1 = __expf(e1);
        {
            float2 f0 = __half22float2(*reinterpret_cast<__half2*>(&v0.x));
            float2 f1 = __half22float2(*reinterpret_cast<__half2*>(&v0.y));
            float2 f2 = __half22float2(*reinterpret_cast<__half2*>(&v0.z));
            float2 f3 = __half22float2(*reinterpret_cast<__half2*>(&v0.w));
            acc[0] += x0 * f0.x; acc[1] += x0 * f0.y;
            acc[2] += x0 * f1.x; acc[3] += x0 * f1.y;
            acc[4] += x0 * f2.x; acc[5] += x0 * f2.y;
            acc[6] += x0 * f3.x; acc[7] += x0 * f3.y;
        }
        {
            float2 f0 = __half22float2(*reinterpret_cast<__half2*>(&v1.x));
            float2 f1 = __half22float2(*reinterpret_cast<__half2*>(&v1.y));
            float2 f2 = __half22float2(*reinterpret_cast<__half2*>(&v1.z));
            float2 f3 = __half22float2(*reinterpret_cast<__half2*>(&v1.w));
            acc[0] += x1 * f0.x; acc[1] += x1 * f0.y;
            acc[2] += x1 * f1.x; acc[3] += x1 * f1.y;
            acc[4] += x1 * f2.x; acc[5] += x1 * f2.y;
            acc[6] += x1 * f3.x; acc[7] += x1 * f3.y;
        }
        den += x0 + x1;
    }
    if (a < end) {
        int s = csr_src[a];
        float e = as_[s * 4 + head] + adv;
        uint4 v = hb[(size_t)s * 32 + lane];
        e = e > 0.f ? e : 0.2f * e;
        float ex = __expf(e);
        float2 f0 = __half22float2(*reinterpret_cast<__half2*>(&v.x));
        float2 f1 = __half22float2(*reinterpret_cast<__half2*>(&v.y));
        float2 f2 = __half22float2(*reinterpret_cast<__half2*>(&v.z));
        float2 f3 = __half22float2(*reinterpret_cast<__half2*>(&v.w));
        acc[0] += ex * f0.x; acc[1] += ex * f0.y;
        acc[2] += ex * f1.x; acc[3] += ex * f1.y;
        acc[4] += ex * f2.x; acc[5] += ex * f2.y;
        acc[6] += ex * f3.x; acc[7] += ex * f3.y;
        den += ex;
    }

    float r = 1.f / (den + 1e-16f);
    float4 b0 = *reinterpret_cast<const float4*>(&bias[lane * 8]);
    float4 b1 = *reinterpret_cast<const float4*>(&bias[lane * 8 + 4]);
    float o[8];
    o[0] = acc[0] * r + b0.x; o[1] = acc[1] * r + b0.y;
    o[2] = acc[2] * r + b0.z; o[3] = acc[3] * r + b0.w;
    o[4] = acc[4] * r + b1.x; o[5] = acc[5] * r + b1.y;
    o[6] = acc[6] * r + b1.z; o[7] = acc[7] * r + b1.w;
#pragma unroll
    for (int k = 0; k < 8; k++) {
        float v = o[k] > 0.f ? o[k] : expm1f(o[k]);
        o[k] = to_tf32(v);   // pre-round for next GEMM's raw tf32 loads
    }
    float4* op = reinterpret_cast<float4*>(out + (size_t)d * HC12 + lane * 8);
    op[0] = make_float4(o[0], o[1], o[2], o[3]);
    op[1] = make_float4(o[4], o[5], o[6], o[7]);
}

// ---------------------------------------------------------------------------
// GAT aggregation (H=1, C=128), fp16 h: ONE warp per dst; lane owns 4 chans.
// ---------------------------------------------------------------------------
__global__ __launch_bounds__(256) void gat_gather1_kernel(
    const int* __restrict__ off, const int* __restrict__ csr_src,
    const __half* __restrict__ h,
    const float* __restrict__ as_, const float* __restrict__ ad_,
    const float* __restrict__ bias, float* __restrict__ out)
{
    int gt   = blockIdx.x * blockDim.x + threadIdx.x;
    int d    = gt >> 5;
    int lane = gt & 31;
    if (d >= NN) return;

    const uint2* hb = reinterpret_cast<const uint2*>(h);
    float adv = ad_[d];
    float acc[4] = {0.f, 0.f, 0.f, 0.f};
    float den = 0.f;

    int a   = off[d];
    int end = off[d + 1];
    for (; a + 1 < end; a += 2) {
        int s0 = csr_src[a];
        int s1 = csr_src[a + 1];
        float e0 = as_[s0] + adv;
        float e1 = as_[s1] + adv;
        uint2 v0 = hb[(size_t)s0 * 32 + lane];
        uint2 v1 = hb[(size_t)s1 * 32 + lane];
        e0 = e0 > 0.f ? e0 : 0.2f * e0;
        e1 = e1 > 0.f ? e1 : 0.2f * e1;
        float x0 = __expf(e0);
        float x1 = __expf(e1);
        {
            float2 f0 = __half22float2(*reinterpret_cast<__half2*>(&v0.x));
            float2 f1 = __half22float2(*reinterpret_cast<__half2*>(&v0.y));
            acc[0] += x0 * f0.x; acc[1] += x0 * f0.y;
            acc[2] += x0 * f1.x; acc[3] += x0 * f1.y;
        }
        {
            float2 f0 = __half22float2(*reinterpret_cast<__half2*>(&v1.x));
            float2 f1 = __half22float2(*reinterpret_cast<__half2*>(&v1.y));
            acc[0] += x1 * f0.x; acc[1] += x1 * f0.y;
            acc[2] += x1 * f1.x; acc[3] += x1 * f1.y;
        }
        den += x0 + x1;
    }
    if (a < end) {
        int s = csr_src[a];
        float e = as_[s] + adv;
        uint2 v = hb[(size_t)s * 32 + lane];
        e = e > 0.f ? e : 0.2f * e;
        float ex = __expf(e);
        float2 f0 = __half22float2(*reinterpret_cast<__half2*>(&v.x));
        float2 f1 = __half22float2(*reinterpret_cast<__half2*>(&v.y));
        acc[0] += ex * f0.x; acc[1] += ex * f0.y;
        acc[2] += ex * f1.x; acc[3] += ex * f1.y;
        den += ex;
    }

    float r = 1.f / (den + 1e-16f);
    float4 b = *reinterpret_cast<const float4*>(&bias[lane * 4]);
    float4 o;
    o.x = acc[0] * r + b.x; o.y = acc[1] * r + b.y;
    o.z = acc[2] * r + b.z; o.w = acc[3] * r + b.w;
    reinterpret_cast<float4*>(out + (size_t)d * FOUT)[lane] = o;
}

// ---------------------------------------------------------------------------
// Global mean pool
// ---------------------------------------------------------------------------
__global__ void pool_cnt_kernel(const int* __restrict__ batch, float* __restrict__ cnt)
{
    int t = blockIdx.x * blockDim.x + threadIdx.x;
    if (t >= NN) return;
    atomicAdd(&cnt[batch[t]], 1.f);
}

__global__ void pool_sum_kernel(const float* __restrict__ h,
                                const int* __restrict__ batch,
                                float* __restrict__ gsum)
{
    int t = blockIdx.x * blockDim.x + threadIdx.x;
    if (t >= NN * FOUT) return;
    int n = t >> 7;
    int c = t & 127;
    atomicAdd(&gsum[batch[n] * FOUT + c], h[t]);
}

__global__ void pool_div_kernel(const float* __restrict__ gsum,
                                const float* __restrict__ cnt,
                                float* __restrict__ out)
{
    int t = blockIdx.x * blockDim.x + threadIdx.x;
    if (t >= GG * FOUT) return;
    out[t] = gsum[t] / fmaxf(cnt[t >> 7], 1.f);
}

// ---------------------------------------------------------------------------
// Launch
// ---------------------------------------------------------------------------
extern "C" void kernel_launch(void* const* d_in, const int* in_sizes, int n_in,
                              void* d_out, int out_size)
{
    const float* x   = (const float*)d_in[0];
    const int*   ei  = (const int*)d_in[1];
    const int*   bat = (const int*)d_in[2];
    const float* W1  = (const float*)d_in[3];
    const float* as1 = (const float*)d_in[4];
    const float* ad1 = (const float*)d_in[5];
    const float* b1  = (const float*)d_in[6];
    const float* W2  = (const float*)d_in[7];
    const float* as2 = (const float*)d_in[8];
    const float* ad2 = (const float*)d_in[9];
    const float* b2  = (const float*)d_in[10];
    const float* W3  = (const float*)d_in[11];
    const float* as3 = (const float*)d_in[12];
    const float* ad3 = (const float*)d_in[13];
    const float* b3  = (const float*)d_in[14];

    float* out     = (float*)d_out;
    float* out_emb = out;                 // [G, FOUT]
    float* out_h   = out + GG * FOUT;     // [N, FOUT]

    __half* h16;
    float *bufB, *xtf, *wtf, *asA, *adA, *asB, *adB, *gsum, *gcnt;
    int *deg, *off, *cur, *csr_src;
    cudaGetSymbolAddress((void**)&h16,  g_h16);
    cudaGetSymbolAddress((void**)&bufB, g_bufB);
    cudaGetSymbolAddress((void**)&xtf,  g_xtf);
    cudaGetSymbolAddress((void**)&wtf,  g_wtf);
    cudaGetSymbolAddress((void**)&asA,  g_asA);
    cudaGetSymbolAddress((void**)&adA,  g_adA);
    cudaGetSymbolAddress((void**)&asB,  g_asB);
    cudaGetSymbolAddress((void**)&adB,  g_adB);
    cudaGetSymbolAddress((void**)&gsum, g_gsum);
    cudaGetSymbolAddress((void**)&gcnt, g_gcnt);
    cudaGetSymbolAddress((void**)&deg,  g_deg);
    cudaGetSymbolAddress((void**)&off,  g_off);
    cudaGetSymbolAddress((void**)&cur,  g_cur);
    cudaGetSymbolAddress((void**)&csr_src, g_csr_src);

    float* wtf1 = wtf;
    float* wtf2 = wtf + 32768;
    float* wtf3 = wtf + 98304;

    // --- pre-round inputs + CSR build ---
    cvt_kernel<<<(NN * FIN + 255) / 256, 256>>>(x, xtf, W1, W2, W3, wtf);
    csr_count_kernel<<<(ETOT + 255) / 256, 256>>>(ei, deg, asA, adA, asB, adB, gsum, gcnt);
    csr_scan_kernel<<<1, 1024>>>(deg, off, cur);
    csr_scatter_kernel<<<(ETOT + 255) / 256, 256>>>(ei, cur, csr_src);

    const int nby = (NN + 127) / 128;
    const int gatherGrid = (NN * 32 + 255) / 256;

    // --- Layer 1 ---
    gemm_tc_kernel<<<dim3(HC12 / 64, nby), 256>>>(xtf, wtf1, h16, NN, FIN, HC12,
                                                  as1, ad1, asA, adA, HEADS, HID);
    gat_gather4_kernel<<<gatherGrid, 256>>>(off, csr_src, h16, asA, adA, b1, bufB,
                                            nullptr, nullptr);

    // --- Layer 2 (alpha into B buffers; gather zeroes A buffers for layer 3) ---
    gemm_tc_kernel<<<dim3(HC12 / 64, nby), 256>>>(bufB, wtf2, h16, NN, HC12, HC12,
                                                  as2, ad2, asB, adB, HEADS, HID);
    gat_gather4_kernel<<<gatherGrid, 256>>>(off, csr_src, h16, asB, adB, b2, bufB,
                                            asA, adA);

    // --- Layer 3 ---
    gemm_tc_kernel<<<dim3(FOUT / 64, nby), 256>>>(bufB, wtf3, h16, NN, HC12, FOUT,
                                                  as3, ad3, asA, adA, 1, FOUT);
    gat_gather1_kernel<<<gatherGrid, 256>>>(off, csr_src, h16, asA, adA, b3, out_h);

    // --- Global mean pool ---
    pool_cnt_kernel<<<(NN + 255) / 256, 256>>>(bat, gcnt);
    pool_sum_kernel<<<(NN * FOUT + 255) / 256, 256>>>(out_h, bat, gsum);
    pool_div_kernel<<<(GG * FOUT + 255) / 256, 256>>>(gsum, gcnt, out_emb);
}

// round 9
// speedup vs baseline: 1.5652x; 1.1878x over previous
#include <cuda_runtime.h>
#include <cuda_fp16.h>
#include <cstdint>

#define NN     20000
#define EE     640000
#define ETOT   660000      // EE + NN self loops
#define GG     64
#define FIN    128
#define FOUT   128
#define HEADS  4
#define HID    64
#define HC12   256         // HEADS*HID

// ---------------------------------------------------------------------------
// Scratch (device globals; zero-initialized at module load)
// ---------------------------------------------------------------------------
__device__ __half g_h16[(size_t)NN * HC12];   // h = x @ W (fp16, gather input)
__device__ float  g_bufB[(size_t)NN * HC12];  // aggregated out (tf32-rounded fp32)
__device__ float  g_xtf[(size_t)NN * FIN];    // x pre-rounded to tf32
__device__ float  g_wtf[131072];              // W1|W2|W3 pre-rounded to tf32
__device__ float  g_asA[(size_t)NN * HEADS];
__device__ float  g_adA[(size_t)NN * HEADS];
__device__ float  g_asB[(size_t)NN * HEADS];
__device__ float  g_adB[(size_t)NN * HEADS];
__device__ int    g_deg[NN];                  // invariant: zero at call entry
__device__ int    g_off[NN + 1];
__device__ int    g_rank[ETOT];
__device__ int    g_csr_src[ETOT];

// ---------------------------------------------------------------------------
// TF32 helpers
// ---------------------------------------------------------------------------
__device__ __forceinline__ float to_tf32(float x) {
    uint32_t u;
    asm("cvt.rna.tf32.f32 %0, %1;" : "=r"(u) : "f"(x));
    return __uint_as_float(u);
}

__device__ __forceinline__ void mma_tf32(float* c, const uint32_t* a, const uint32_t* b) {
    asm volatile(
        "mma.sync.aligned.m16n8k8.row.col.f32.tf32.tf32.f32 "
        "{%0,%1,%2,%3}, {%4,%5,%6,%7}, {%8,%9}, {%0,%1,%2,%3};"
        : "+f"(c[0]), "+f"(c[1]), "+f"(c[2]), "+f"(c[3])
        : "r"(a[0]), "r"(a[1]), "r"(a[2]), "r"(a[3]), "r"(b[0]), "r"(b[1]));
}

// ---------------------------------------------------------------------------
// Pre-round inputs to tf32 (float4) + zero the alpha accumulators
// ---------------------------------------------------------------------------
__global__ void cvt_kernel(const float4* __restrict__ x, float4* __restrict__ xtf,
                           const float4* __restrict__ W1, const float4* __restrict__ W2,
                           const float4* __restrict__ W3, float4* __restrict__ wtf,
                           float* __restrict__ asA, float* __restrict__ adA,
                           float* __restrict__ asB, float* __restrict__ adB)
{
    int t = blockIdx.x * blockDim.x + threadIdx.x;
    if (t < NN * HEADS) { asA[t] = 0.f; adA[t] = 0.f; asB[t] = 0.f; adB[t] = 0.f; }
    if (t < NN * FIN / 4) {
        float4 v = x[t];
        v.x = to_tf32(v.x); v.y = to_tf32(v.y);
        v.z = to_tf32(v.z); v.w = to_tf32(v.w);
        xtf[t] = v;
    }
    if (t < 32768) {
        float4 v;
        if (t < 8192)       v = W1[t];
        else if (t < 24576) v = W2[t - 8192];
        else                v = W3[t - 24576];
        v.x = to_tf32(v.x); v.y = to_tf32(v.y);
        v.z = to_tf32(v.z); v.w = to_tf32(v.w);
        wtf[t] = v;
    }
}

// ---------------------------------------------------------------------------
// Double-buffered TF32 GEMM with fused alpha epilogue.
// ---------------------------------------------------------------------------
__global__ __launch_bounds__(256) void gemm_tc_kernel(
    const float* __restrict__ A, const float* __restrict__ B,
    __half* __restrict__ C, int N, int K, int M,
    const float* __restrict__ avs, const float* __restrict__ avd,
    float* __restrict__ outs, float* __restrict__ outd, int H, int Cdim)
{
    __shared__ float As[2][128][20];
    __shared__ float Bs[2][16][72];

    const int tid  = threadIdx.x;
    const int lane = tid & 31;
    const int warp = tid >> 5;
    const int wr   = (warp & 3) * 32;
    const int wc   = (warp >> 2) * 32;
    const int rowBase = blockIdx.y * 128;
    const int colBase = blockIdx.x * 64;
    const int g  = lane >> 2;
    const int tg = lane & 3;

    const int ar0 = tid >> 2;
    const int ac4 = (tid & 3) * 4;
    const int br  = tid >> 4;
    const int bc4 = (tid & 15) * 4;

    float acc[2][4][4];
#pragma unroll
    for (int i = 0; i < 2; i++)
#pragma unroll
        for (int j = 0; j < 4; j++)
#pragma unroll
            for (int k = 0; k < 4; k++) acc[i][j][k] = 0.f;

    auto stage = [&](int k0, int st) {
#pragma unroll
        for (int l = 0; l < 2; l++) {
            int r  = ar0 + l * 64;
            int gr = rowBase + r;
            uint32_t dst = (uint32_t)__cvta_generic_to_shared(&As[st][r][ac4]);
            const float* src = (gr < N) ? &A[(size_t)gr * K + k0 + ac4] : A;
            int sz = (gr < N) ? 16 : 0;
            asm volatile("cp.async.cg.shared.global [%0], [%1], 16, %2;"
                         :: "r"(dst), "l"(src), "r"(sz));
        }
        {
            uint32_t dst = (uint32_t)__cvta_generic_to_shared(&Bs[st][br][bc4]);
            const float* src = &B[(size_t)(k0 + br) * M + colBase + bc4];
            asm volatile("cp.async.cg.shared.global [%0], [%1], 16;"
                         :: "r"(dst), "l"(src));
        }
        asm volatile("cp.async.commit_group;");
    };

    const int T = K >> 4;
    stage(0, 0);
    for (int it = 0; it < T; it++) {
        if (it + 1 < T) {
            stage((it + 1) << 4, (it + 1) & 1);
            asm volatile("cp.async.wait_group 1;");
        } else {
            asm volatile("cp.async.wait_group 0;");
        }
        __syncthreads();
        int st = it & 1;
#pragma unroll
        for (int kk = 0; kk < 16; kk += 8) {
            uint32_t a[2][4], b[4][2];
#pragma unroll
            for (int i = 0; i < 2; i++) {
                int r0 = wr + i * 16 + g;
                a[i][0] = __float_as_uint(As[st][r0][kk + tg]);
                a[i][1] = __float_as_uint(As[st][r0 + 8][kk + tg]);
                a[i][2] = __float_as_uint(As[st][r0][kk + 4 + tg]);
                a[i][3] = __float_as_uint(As[st][r0 + 8][kk + 4 + tg]);
            }
#pragma unroll
            for (int j = 0; j < 4; j++) {
                int c0 = wc + j * 8 + g;
                b[j][0] = __float_as_uint(Bs[st][kk + tg][c0]);
                b[j][1] = __float_as_uint(Bs[st][kk + 4 + tg][c0]);
            }
#pragma unroll
            for (int i = 0; i < 2; i++)
#pragma unroll
                for (int j = 0; j < 4; j++)
                    mma_tf32(acc[i][j], a[i], b[j]);
        }
        __syncthreads();
    }

    // ---- writeback fp16 C ----
#pragma unroll
    for (int i = 0; i < 2; i++) {
        int r0 = rowBase + wr + i * 16 + g;
#pragma unroll
        for (int j = 0; j < 4; j++) {
            int c0 = colBase + wc + j * 8 + tg * 2;
            if (r0 < N) {
                __half2 v = __floats2half2_rn(acc[i][j][0], acc[i][j][1]);
                *reinterpret_cast<__half2*>(&C[(size_t)r0 * M + c0]) = v;
            }
            if (r0 + 8 < N) {
                __half2 v = __floats2half2_rn(acc[i][j][2], acc[i][j][3]);
                *reinterpret_cast<__half2*>(&C[(size_t)(r0 + 8) * M + c0]) = v;
            }
        }
    }

    // ---- fused alpha partials ----
    const int head = colBase / Cdim;
    float ps[2][2], pd[2][2];
#pragma unroll
    for (int i = 0; i < 2; i++) { ps[i][0]=ps[i][1]=pd[i][0]=pd[i][1]=0.f; }
#pragma unroll
    for (int j = 0; j < 4; j++) {
        int c0 = colBase + wc + j * 8 + tg * 2;
        float s0 = avs[c0], s1 = avs[c0 + 1];
        float d0 = avd[c0], d1 = avd[c0 + 1];
#pragma unroll
        for (int i = 0; i < 2; i++) {
            ps[i][0] += acc[i][j][0] * s0 + acc[i][j][1] * s1;
            pd[i][0] += acc[i][j][0] * d0 + acc[i][j][1] * d1;
            ps[i][1] += acc[i][j][2] * s0 + acc[i][j][3] * s1;
            pd[i][1] += acc[i][j][2] * d0 + acc[i][j][3] * d1;
        }
    }
#pragma unroll
    for (int o = 1; o < 4; o <<= 1) {
#pragma unroll
        for (int i = 0; i < 2; i++) {
#pragma unroll
            for (int sr = 0; sr < 2; sr++) {
                ps[i][sr] += __shfl_xor_sync(0xffffffffu, ps[i][sr], o);
                pd[i][sr] += __shfl_xor_sync(0xffffffffu, pd[i][sr], o);
            }
        }
    }
    if (tg == 0) {
#pragma unroll
        for (int i = 0; i < 2; i++) {
            int ra = rowBase + wr + i * 16 + g;
            if (ra < N) {
                atomicAdd(&outs[ra * H + head], ps[i][0]);
                atomicAdd(&outd[ra * H + head], pd[i][0]);
            }
            int rb = ra + 8;
            if (rb < N) {
                atomicAdd(&outs[rb * H + head], ps[i][1]);
                atomicAdd(&outd[rb * H + head], pd[i][1]);
            }
        }
    }
}

// ---------------------------------------------------------------------------
// CSR count: deg histogram + per-edge rank (position within dst bucket)
// ---------------------------------------------------------------------------
__global__ void csr_count_kernel(const int* __restrict__ ei, int* __restrict__ deg,
                                 int* __restrict__ rank)
{
    int t = blockIdx.x * blockDim.x + threadIdx.x;
    if (t >= ETOT) return;
    int d = (t < EE) ? ei[EE + t] : (t - EE);
    rank[t] = atomicAdd(&deg[d], 1);
}

// single block scan; re-zeroes deg after reading
__global__ __launch_bounds__(1024) void csr_scan_kernel(
    int* __restrict__ deg, int* __restrict__ off)
{
    const int PER = 20;
    __shared__ int warpSums[32];
    int t    = threadIdx.x;
    int lane = t & 31, wid = t >> 5;
    int base = t * PER;

    int v[PER];
    int s = 0;
#pragma unroll
    for (int i = 0; i < PER; i++) {
        int idx = base + i;
        int x = (idx < NN) ? deg[idx] : 0;
        if (idx < NN) deg[idx] = 0;
        v[i] = s;
        s += x;
    }
    int incl = s;
#pragma unroll
    for (int o = 1; o < 32; o <<= 1) {
        int u = __shfl_up_sync(0xffffffffu, incl, o);
        if (lane >= o) incl += u;
    }
    if (lane == 31) warpSums[wid] = incl;
    __syncthreads();
    if (wid == 0) {
        int ws = warpSums[lane];
#pragma unroll
        for (int o = 1; o < 32; o <<= 1) {
            int u = __shfl_up_sync(0xffffffffu, ws, o);
            if (lane >= o) ws += u;
        }
        warpSums[lane] = ws;
    }
    __syncthreads();
    int warpPrefix  = (wid == 0) ? 0 : warpSums[wid - 1];
    int threadExcl  = warpPrefix + incl - s;
#pragma unroll
    for (int i = 0; i < PER; i++) {
        int idx = base + i;
        if (idx < NN) off[idx] = threadExcl + v[i];
    }
    if (t == 0) off[NN] = ETOT;
}

// atomic-free scatter using precomputed ranks
__global__ void csr_scatter_kernel(const int* __restrict__ ei,
                                   const int* __restrict__ off,
                                   const int* __restrict__ rank,
                                   int* __restrict__ csr_src)
{
    int t = blockIdx.x * blockDim.x + threadIdx.x;
    if (t >= ETOT) return;
    int s, d;
    if (t < EE) { s = ei[t]; d = ei[EE + t]; }
    else        { s = t - EE; d = s; }
    csr_src[off[d] + rank[t]] = s;
}

// ---------------------------------------------------------------------------
// GAT aggregation (H=4, C=64), fp16 h: ONE warp per dst node; unroll-2 edges.
// Output tf32-rounded. Optional tail zeroes alpha buffers for a later layer.
// ---------------------------------------------------------------------------
__global__ __launch_bounds__(256) void gat_gather4_kernel(
    const int* __restrict__ off, const int* __restrict__ csr_src,
    const __half* __restrict__ h,
    const float* __restrict__ as_, const float* __restrict__ ad_,
    const float* __restrict__ bias, float* __restrict__ out,
    float* __restrict__ za, float* __restrict__ zd)
{
    int gt   = blockIdx.x * blockDim.x + threadIdx.x;
    if (za != nullptr && gt < NN * HEADS) { za[gt] = 0.f; zd[gt] = 0.f; }
    int d    = gt >> 5;
    int lane = gt & 31;
    if (d >= NN) return;

    const int head = lane >> 3;
    const uint4* hb = reinterpret_cast<const uint4*>(h);
    float adv = ad_[d * 4 + head];

    float acc[8];
#pragma unroll
    for (int k = 0; k < 8; k++) acc[k] = 0.f;
    float den = 0.f;

    int a   = off[d];
    int end = off[d + 1];
    for (; a + 1 < end; a += 2) {
        int s0 = csr_src[a];
        int s1 = csr_src[a + 1];
        float e0 = as_[s0 * 4 + head] + adv;
        float e1 = as_[s1 * 4 + head] + adv;
        uint4 v0 = hb[(size_t)s0 * 32 + lane];
        uint4 v1 = hb[(size_t)s1 * 32 + lane];
        e0 = e0 > 0.f ? e0 : 0.2f * e0;
        e1 = e1 > 0.f ? e1 : 0.2f * e1;
        float x0 = __expf(e0);
        float x1 = __expf(e1);
        {
            float2 f0 = __half22float2(*reinterpret_cast<__half2*>(&v0.x));
            float2 f1 = __half22float2(*reinterpret_cast<__half2*>(&v0.y));
            float2 f2 = __half22float2(*reinterpret_cast<__half2*>(&v0.z));
            float2 f3 = __half22float2(*reinterpret_cast<__half2*>(&v0.w));
            acc[0] += x0 * f0.x; acc[1] += x0 * f0.y;
            acc[2] += x0 * f1.x; acc[3] += x0 * f1.y;
            acc[4] += x0 * f2.x; acc[5] += x0 * f2.y;
            acc[6] += x0 * f3.x; acc[7] += x0 * f3.y;
        }
        {
            float2 f0 = __half22float2(*reinterpret_cast<__half2*>(&v1.x));
            float2 f1 = __half22float2(*reinterpret_cast<__half2*>(&v1.y));
            float2 f2 = __half22float2(*reinterpret_cast<__half2*>(&v1.z));
            float2 f3 = __half22float2(*reinterpret_cast<__half2*>(&v1.w));
            acc[0] += x1 * f0.x; acc[1] += x1 * f0.y;
            acc[2] += x1 * f1.x; acc[3] += x1 * f1.y;
            acc[4] += x1 * f2.x; acc[5] += x1 * f2.y;
            acc[6] += x1 * f3.x; acc[7] += x1 * f3.y;
        }
        den += x0 + x1;
    }
    if (a < end) {
        int s = csr_src[a];
        float e = as_[s * 4 + head] + adv;
        uint4 v = hb[(size_t)s * 32 + lane];
        e = e > 0.f ? e : 0.2f * e;
        float ex = __expf(e);
        float2 f0 = __half22float2(*reinterpret_cast<__half2*>(&v.x));
        float2 f1 = __half22float2(*reinterpret_cast<__half2*>(&v.y));
        float2 f2 = __half22float2(*reinterpret_cast<__half2*>(&v.z));
        float2 f3 = __half22float2(*reinterpret_cast<__half2*>(&v.w));
        acc[0] += ex * f0.x; acc[1] += ex * f0.y;
        acc[2] += ex * f1.x; acc[3] += ex * f1.y;
        acc[4] += ex * f2.x; acc[5] += ex * f2.y;
        acc[6] += ex * f3.x; acc[7] += ex * f3.y;
        den += ex;
    }

    float r = 1.f / (den + 1e-16f);
    float4 b0 = *reinterpret_cast<const float4*>(&bias[lane * 8]);
    float4 b1 = *reinterpret_cast<const float4*>(&bias[lane * 8 + 4]);
    float o[8];
    o[0] = acc[0] * r + b0.x; o[1] = acc[1] * r + b0.y;
    o[2] = acc[2] * r + b0.z; o[3] = acc[3] * r + b0.w;
    o[4] = acc[4] * r + b1.x; o[5] = acc[5] * r + b1.y;
    o[6] = acc[6] * r + b1.z; o[7] = acc[7] * r + b1.w;
#pragma unroll
    for (int k = 0; k < 8; k++) {
        float v = o[k] > 0.f ? o[k] : expm1f(o[k]);
        o[k] = to_tf32(v);
    }
    float4* op = reinterpret_cast<float4*>(out + (size_t)d * HC12 + lane * 8);
    op[0] = make_float4(o[0], o[1], o[2], o[3]);
    op[1] = make_float4(o[4], o[5], o[6], o[7]);
}

// ---------------------------------------------------------------------------
// GAT aggregation (H=1, C=128), fp16 h: ONE warp per dst; lane owns 4 chans.
// ---------------------------------------------------------------------------
__global__ __launch_bounds__(256) void gat_gather1_kernel(
    const int* __restrict__ off, const int* __restrict__ csr_src,
    const __half* __restrict__ h,
    const float* __restrict__ as_, const float* __restrict__ ad_,
    const float* __restrict__ bias, float* __restrict__ out)
{
    int gt   = blockIdx.x * blockDim.x + threadIdx.x;
    int d    = gt >> 5;
    int lane = gt & 31;
    if (d >= NN) return;

    const uint2* hb = reinterpret_cast<const uint2*>(h);
    float adv = ad_[d];
    float acc[4] = {0.f, 0.f, 0.f, 0.f};
    float den = 0.f;

    int a   = off[d];
    int end = off[d + 1];
    for (; a + 1 < end; a += 2) {
        int s0 = csr_src[a];
        int s1 = csr_src[a + 1];
        float e0 = as_[s0] + adv;
        float e1 = as_[s1] + adv;
        uint2 v0 = hb[(size_t)s0 * 32 + lane];
        uint2 v1 = hb[(size_t)s1 * 32 + lane];
        e0 = e0 > 0.f ? e0 : 0.2f * e0;
        e1 = e1 > 0.f ? e1 : 0.2f * e1;
        float x0 = __expf(e0);
        float x1 = __expf(e1);
        {
            float2 f0 = __half22float2(*reinterpret_cast<__half2*>(&v0.x));
            float2 f1 = __half22float2(*reinterpret_cast<__half2*>(&v0.y));
            acc[0] += x0 * f0.x; acc[1] += x0 * f0.y;
            acc[2] += x0 * f1.x; acc[3] += x0 * f1.y;
        }
        {
            float2 f0 = __half22float2(*reinterpret_cast<__half2*>(&v1.x));
            float2 f1 = __half22float2(*reinterpret_cast<__half2*>(&v1.y));
            acc[0] += x1 * f0.x; acc[1] += x1 * f0.y;
            acc[2] += x1 * f1.x; acc[3] += x1 * f1.y;
        }
        den += x0 + x1;
    }
    if (a < end) {
        int s = csr_src[a];
        float e = as_[s] + adv;
        uint2 v = hb[(size_t)s * 32 + lane];
        e = e > 0.f ? e : 0.2f * e;
        float ex = __expf(e);
        float2 f0 = __half22float2(*reinterpret_cast<__half2*>(&v.x));
        float2 f1 = __half22float2(*reinterpret_cast<__half2*>(&v.y));
        acc[0] += ex * f0.x; acc[1] += ex * f0.y;
        acc[2] += ex * f1.x; acc[3] += ex * f1.y;
        den += ex;
    }

    float r = 1.f / (den + 1e-16f);
    float4 b = *reinterpret_cast<const float4*>(&bias[lane * 4]);
    float4 o;
    o.x = acc[0] * r + b.x; o.y = acc[1] * r + b.y;
    o.z = acc[2] * r + b.z; o.w = acc[3] * r + b.w;
    reinterpret_cast<float4*>(out + (size_t)d * FOUT)[lane] = o;
}

// ---------------------------------------------------------------------------
// Segmented global mean pool: batch is sorted -> graph g is a contiguous
// node range. One block per graph; thread c owns channel c.
// ---------------------------------------------------------------------------
__global__ __launch_bounds__(128) void pool_kernel(
    const float* __restrict__ h, const int* __restrict__ bat,
    float* __restrict__ out_emb)
{
    int g = blockIdx.x;
    int c = threadIdx.x;

    int lo = 0, hi = NN;
    while (lo < hi) { int m = (lo + hi) >> 1; if (bat[m] < g) lo = m + 1; else hi = m; }
    int start = lo;
    lo = 0; hi = NN;
    while (lo < hi) { int m = (lo + hi) >> 1; if (bat[m] < g + 1) lo = m + 1; else hi = m; }
    int end = lo;

    float s0 = 0.f, s1 = 0.f, s2 = 0.f, s3 = 0.f;
    int n = start;
    for (; n + 3 < end; n += 4) {
        s0 += h[(size_t)n * FOUT + c];
        s1 += h[(size_t)(n + 1) * FOUT + c];
        s2 += h[(size_t)(n + 2) * FOUT + c];
        s3 += h[(size_t)(n + 3) * FOUT + c];
    }
    for (; n < end; n++) s0 += h[(size_t)n * FOUT + c];
    float s = (s0 + s1) + (s2 + s3);
    out_emb[g * FOUT + c] = s / fmaxf((float)(end - start), 1.f);
}

// ---------------------------------------------------------------------------
// Launch
// ---------------------------------------------------------------------------
extern "C" void kernel_launch(void* const* d_in, const int* in_sizes, int n_in,
                              void* d_out, int out_size)
{
    const float* x   = (const float*)d_in[0];
    const int*   ei  = (const int*)d_in[1];
    const int*   bat = (const int*)d_in[2];
    const float* W1  = (const float*)d_in[3];
    const float* as1 = (const float*)d_in[4];
    const float* ad1 = (const float*)d_in[5];
    const float* b1  = (const float*)d_in[6];
    const float* W2  = (const float*)d_in[7];
    const float* as2 = (const float*)d_in[8];
    const float* ad2 = (const float*)d_in[9];
    const float* b2  = (const float*)d_in[10];
    const float* W3  = (const float*)d_in[11];
    const float* as3 = (const float*)d_in[12];
    const float* ad3 = (const float*)d_in[13];
    const float* b3  = (const float*)d_in[14];

    float* out     = (float*)d_out;
    float* out_emb = out;                 // [G, FOUT]
    float* out_h   = out + GG * FOUT;     // [N, FOUT]

    __half* h16;
    float *bufB, *xtf, *wtf, *asA, *adA, *asB, *adB;
    int *deg, *off, *rank, *csr_src;
    cudaGetSymbolAddress((void**)&h16,  g_h16);
    cudaGetSymbolAddress((void**)&bufB, g_bufB);
    cudaGetSymbolAddress((void**)&xtf,  g_xtf);
    cudaGetSymbolAddress((void**)&wtf,  g_wtf);
    cudaGetSymbolAddress((void**)&asA,  g_asA);
    cudaGetSymbolAddress((void**)&adA,  g_adA);
    cudaGetSymbolAddress((void**)&asB,  g_asB);
    cudaGetSymbolAddress((void**)&adB,  g_adB);
    cudaGetSymbolAddress((void**)&deg,  g_deg);
    cudaGetSymbolAddress((void**)&off,  g_off);
    cudaGetSymbolAddress((void**)&rank, g_rank);
    cudaGetSymbolAddress((void**)&csr_src, g_csr_src);

    float* wtf1 = wtf;
    float* wtf2 = wtf + 32768;
    float* wtf3 = wtf + 98304;

    // Lazily created side stream + events (capture-legal fork/join)
    static cudaStream_t sideStream = nullptr;
    static cudaEvent_t evFork = nullptr, evJoin = nullptr;
    if (sideStream == nullptr) {
        cudaStreamCreateWithFlags(&sideStream, cudaStreamNonBlocking);
        cudaEventCreateWithFlags(&evFork, cudaEventDisableTiming);
        cudaEventCreateWithFlags(&evJoin, cudaEventDisableTiming);
    }

    // --- fork: CSR build on side stream ---
    cudaEventRecord(evFork, 0);
    cudaStreamWaitEvent(sideStream, evFork, 0);
    csr_count_kernel<<<(ETOT + 255) / 256, 256, 0, sideStream>>>(ei, deg, rank);
    csr_scan_kernel<<<1, 1024, 0, sideStream>>>(deg, off);
    csr_scatter_kernel<<<(ETOT + 255) / 256, 256, 0, sideStream>>>(ei, off, rank, csr_src);
    cudaEventRecord(evJoin, sideStream);

    const int nby = (NN + 127) / 128;
    const int gatherGrid = (NN * 32 + 255) / 256;

    // --- main stream: cvt + layer-1 GEMM overlap with CSR ---
    cvt_kernel<<<(NN * FIN / 4 + 255) / 256, 256>>>(
        (const float4*)x, (float4*)xtf, (const float4*)W1, (const float4*)W2,
        (const float4*)W3, (float4*)wtf, asA, adA, asB, adB);
    gemm_tc_kernel<<<dim3(HC12 / 64, nby), 256>>>(xtf, wtf1, h16, NN, FIN, HC12,
                                                  as1, ad1, asA, adA, HEADS, HID);

    // --- join: gathers need the CSR ---
    cudaStreamWaitEvent(0, evJoin, 0);

    gat_gather4_kernel<<<gatherGrid, 256>>>(off, csr_src, h16, asA, adA, b1, bufB,
                                            nullptr, nullptr);

    // --- Layer 2 ---
    gemm_tc_kernel<<<dim3(HC12 / 64, nby), 256>>>(bufB, wtf2, h16, NN, HC12, HC12,
                                                  as2, ad2, asB, adB, HEADS, HID);
    gat_gather4_kernel<<<gatherGrid, 256>>>(off, csr_src, h16, asB, adB, b2, bufB,
                                            asA, adA);

    // --- Layer 3 ---
    gemm_tc_kernel<<<dim3(FOUT / 64, nby), 256>>>(bufB, wtf3, h16, NN, HC12, FOUT,
                                                  as3, ad3, asA, adA, 1, FOUT);
    gat_gather1_kernel<<<gatherGrid, 256>>>(off, csr_src, h16, asA, adA, b3, out_h);

    // --- segmented global mean pool ---
    pool_kernel<<<GG, 128>>>(out_h, bat, out_emb);
}

// round 11
// speedup vs baseline: 1.6699x; 1.0669x over previous
#include <cuda_runtime.h>
#include <cuda_fp16.h>
#include <cstdint>
#include <cstring>

#define NN     20000
#define EE     640000
#define ETOT   660000      // EE + NN self loops
#define GG     64
#define FIN    128
#define FOUT   128
#define HEADS  4
#define HID    64
#define HC12   256         // HEADS*HID

// ---------------------------------------------------------------------------
// Scratch (device globals; zero-initialized at module load)
// ---------------------------------------------------------------------------
__device__ __half g_h16[(size_t)NN * HC12];   // GEMM out (gather input)
__device__ __half g_b16[(size_t)NN * HC12];   // gather out (next GEMM input)
__device__ __half g_x16[(size_t)NN * FIN];    // x in fp16
__device__ __half g_w16[131072];              // W1|W2|W3 in fp16
__device__ float  g_asA[(size_t)NN * HEADS];
__device__ float  g_adA[(size_t)NN * HEADS];
__device__ float  g_asB[(size_t)NN * HEADS];
__device__ float  g_adB[(size_t)NN * HEADS];
__device__ int    g_deg[NN];                  // invariant: zero at call entry
__device__ int    g_off[NN + 1];
__device__ int    g_rank[ETOT];
__device__ int    g_csr_src[ETOT];

// ---------------------------------------------------------------------------
// Helpers
// ---------------------------------------------------------------------------
__device__ __forceinline__ uint32_t h2_as_u32(__half2 h) {
    uint32_t u;
    memcpy(&u, &h, 4);
    return u;
}

__device__ __forceinline__ void mma_f16(float* c, const uint32_t* a, const uint32_t* b) {
    asm volatile(
        "mma.sync.aligned.m16n8k16.row.col.f32.f16.f16.f32 "
        "{%0,%1,%2,%3}, {%4,%5,%6,%7}, {%8,%9}, {%0,%1,%2,%3};"
        : "+f"(c[0]), "+f"(c[1]), "+f"(c[2]), "+f"(c[3])
        : "r"(a[0]), "r"(a[1]), "r"(a[2]), "r"(a[3]), "r"(b[0]), "r"(b[1]));
}

__device__ __forceinline__ void ldsm_x4(uint32_t* r, uint32_t addr) {
    asm volatile("ldmatrix.sync.aligned.m8n8.x4.shared.b16 {%0,%1,%2,%3}, [%4];"
                 : "=r"(r[0]), "=r"(r[1]), "=r"(r[2]), "=r"(r[3]) : "r"(addr));
}

__device__ __forceinline__ void ldsm_x4_trans(uint32_t* r, uint32_t addr) {
    asm volatile("ldmatrix.sync.aligned.m8n8.x4.trans.shared.b16 {%0,%1,%2,%3}, [%4];"
                 : "=r"(r[0]), "=r"(r[1]), "=r"(r[2]), "=r"(r[3]) : "r"(addr));
}

// ---------------------------------------------------------------------------
// Convert x and W1|W2|W3 to fp16 + zero alpha accumulators
// ---------------------------------------------------------------------------
__global__ void cvt_kernel(const float4* __restrict__ x, uint2* __restrict__ x16,
                           const float4* __restrict__ W1, const float4* __restrict__ W2,
                           const float4* __restrict__ W3, uint2* __restrict__ w16,
                           float* __restrict__ asA, float* __restrict__ adA,
                           float* __restrict__ asB, float* __restrict__ adB)
{
    int t = blockIdx.x * blockDim.x + threadIdx.x;
    if (t < NN * HEADS) { asA[t] = 0.f; adA[t] = 0.f; asB[t] = 0.f; adB[t] = 0.f; }
    if (t < NN * FIN / 4) {
        float4 v = x[t];
        uint2 o;
        o.x = h2_as_u32(__floats2half2_rn(v.x, v.y));
        o.y = h2_as_u32(__floats2half2_rn(v.z, v.w));
        x16[t] = o;
    }
    if (t < 32768) {
        float4 v;
        if (t < 8192)       v = W1[t];
        else if (t < 24576) v = W2[t - 8192];
        else                v = W3[t - 24576];
        uint2 o;
        o.x = h2_as_u32(__floats2half2_rn(v.x, v.y));
        o.y = h2_as_u32(__floats2half2_rn(v.z, v.w));
        w16[t] = o;
    }
}

// ---------------------------------------------------------------------------
// fp16 tensor-core GEMM, cp.async double-buffered, ldmatrix fragments.
// C16[N,M] = A[N,K]*B[K,M]; fused alpha epilogue into outs/outd (atomic).
// BM=128, BN=64, BK=32; 8 warps x (32x32); mma m16n8k16.
// ---------------------------------------------------------------------------
__global__ __launch_bounds__(256) void gemm_tc_kernel(
    const __half* __restrict__ A, const __half* __restrict__ B,
    __half* __restrict__ C, int N, int K, int M,
    const float* __restrict__ avs, const float* __restrict__ avd,
    float* __restrict__ outs, float* __restrict__ outd, int H, int Cdim)
{
    __shared__ __half As[2][128][40];   // stride 40 halves -> conflict-free ldmatrix
    __shared__ __half Bs[2][32][72];    // stride 72 halves -> conflict-free ldmatrix.trans

    const int tid  = threadIdx.x;
    const int lane = tid & 31;
    const int warp = tid >> 5;
    const int wr   = (warp & 3) * 32;
    const int wc   = (warp >> 2) * 32;
    const int rowBase = blockIdx.y * 128;
    const int colBase = blockIdx.x * 64;
    const int g  = lane >> 2;
    const int tg = lane & 3;
    const int grp  = lane >> 3;
    const int lrow = lane & 7;

    const int ar0 = tid >> 2;            // A: 4 chunks of 8 halves per row
    const int ac8 = (tid & 3) * 8;
    const int brr = tid >> 3;            // B: 8 chunks per row (64 halves)
    const int bc8 = (tid & 7) * 8;

    float acc[2][4][4];
#pragma unroll
    for (int i = 0; i < 2; i++)
#pragma unroll
        for (int j = 0; j < 4; j++)
#pragma unroll
            for (int k = 0; k < 4; k++) acc[i][j][k] = 0.f;

    auto stage = [&](int k0, int st) {
#pragma unroll
        for (int l = 0; l < 2; l++) {
            int r  = ar0 + l * 64;
            int gr = rowBase + r;
            uint32_t dst = (uint32_t)__cvta_generic_to_shared(&As[st][r][ac8]);
            const __half* src = (gr < N) ? &A[(size_t)gr * K + k0 + ac8] : A;
            int sz = (gr < N) ? 16 : 0;
            asm volatile("cp.async.cg.shared.global [%0], [%1], 16, %2;"
                         :: "r"(dst), "l"(src), "r"(sz));
        }
        {
            uint32_t dst = (uint32_t)__cvta_generic_to_shared(&Bs[st][brr][bc8]);
            const __half* src = &B[(size_t)(k0 + brr) * M + colBase + bc8];
            asm volatile("cp.async.cg.shared.global [%0], [%1], 16;"
                         :: "r"(dst), "l"(src));
        }
        asm volatile("cp.async.commit_group;");
    };

    const uint32_t asb = (uint32_t)__cvta_generic_to_shared(&As[0][0][0]);
    const uint32_t bsb = (uint32_t)__cvta_generic_to_shared(&Bs[0][0][0]);
    const uint32_t asStage = 128 * 40 * 2;
    const uint32_t bsStage = 32 * 72 * 2;

    const int T = K >> 5;
    stage(0, 0);
    for (int it = 0; it < T; it++) {
        if (it + 1 < T) {
            stage((it + 1) << 5, (it + 1) & 1);
            asm volatile("cp.async.wait_group 1;");
        } else {
            asm volatile("cp.async.wait_group 0;");
        }
        __syncthreads();
        int st = it & 1;
        uint32_t aS = asb + st * asStage;
        uint32_t bS = bsb + st * bsStage;
#pragma unroll
        for (int kk = 0; kk < 32; kk += 16) {
            uint32_t a[2][4], b[2][4];
#pragma unroll
            for (int i = 0; i < 2; i++) {
                int row = wr + i * 16 + lrow + ((grp & 1) << 3);
                int col = kk + ((grp & 2) << 2);
                ldsm_x4(a[i], aS + (row * 40 + col) * 2);
            }
#pragma unroll
            for (int jp = 0; jp < 2; jp++) {
                int krow = kk + ((grp & 1) << 3) + lrow;
                int ncol = wc + jp * 16 + ((grp & 2) << 2);
                ldsm_x4_trans(b[jp], bS + (krow * 72 + ncol) * 2);
            }
#pragma unroll
            for (int i = 0; i < 2; i++)
#pragma unroll
                for (int j = 0; j < 4; j++)
                    mma_f16(acc[i][j], a[i], &b[j >> 1][(j & 1) * 2]);
        }
        __syncthreads();
    }

    // ---- writeback fp16 C ----
#pragma unroll
    for (int i = 0; i < 2; i++) {
        int r0 = rowBase + wr + i * 16 + g;
#pragma unroll
        for (int j = 0; j < 4; j++) {
            int c0 = colBase + wc + j * 8 + tg * 2;
            if (r0 < N) {
                __half2 v = __floats2half2_rn(acc[i][j][0], acc[i][j][1]);
                *reinterpret_cast<__half2*>(&C[(size_t)r0 * M + c0]) = v;
            }
            if (r0 + 8 < N) {
                __half2 v = __floats2half2_rn(acc[i][j][2], acc[i][j][3]);
                *reinterpret_cast<__half2*>(&C[(size_t)(r0 + 8) * M + c0]) = v;
            }
        }
    }

    // ---- fused alpha partials ----
    const int head = colBase / Cdim;
    float ps[2][2], pd[2][2];
#pragma unroll
    for (int i = 0; i < 2; i++) { ps[i][0]=ps[i][1]=pd[i][0]=pd[i][1]=0.f; }
#pragma unroll
    for (int j = 0; j < 4; j++) {
        int c0 = colBase + wc + j * 8 + tg * 2;
        float s0 = avs[c0], s1 = avs[c0 + 1];
        float d0 = avd[c0], d1 = avd[c0 + 1];
#pragma unroll
        for (int i = 0; i < 2; i++) {
            ps[i][0] += acc[i][j][0] * s0 + acc[i][j][1] * s1;
            pd[i][0] += acc[i][j][0] * d0 + acc[i][j][1] * d1;
            ps[i][1] += acc[i][j][2] * s0 + acc[i][j][3] * s1;
            pd[i][1] += acc[i][j][2] * d0 + acc[i][j][3] * d1;
        }
    }
#pragma unroll
    for (int o = 1; o < 4; o <<= 1) {
#pragma unroll
        for (int i = 0; i < 2; i++) {
#pragma unroll
            for (int sr = 0; sr < 2; sr++) {
                ps[i][sr] += __shfl_xor_sync(0xffffffffu, ps[i][sr], o);
                pd[i][sr] += __shfl_xor_sync(0xffffffffu, pd[i][sr], o);
            }
        }
    }
    if (tg == 0) {
#pragma unroll
        for (int i = 0; i < 2; i++) {
            int ra = rowBase + wr + i * 16 + g;
            if (ra < N) {
                atomicAdd(&outs[ra * H + head], ps[i][0]);
                atomicAdd(&outd[ra * H + head], pd[i][0]);
            }
            int rb = ra + 8;
            if (rb < N) {
                atomicAdd(&outs[rb * H + head], ps[i][1]);
                atomicAdd(&outd[rb * H + head], pd[i][1]);
            }
        }
    }
}

// ---------------------------------------------------------------------------
// CSR build
// ---------------------------------------------------------------------------
__global__ void csr_count_kernel(const int* __restrict__ ei, int* __restrict__ deg,
                                 int* __restrict__ rank)
{
    int t = blockIdx.x * blockDim.x + threadIdx.x;
    if (t >= ETOT) return;
    int d = (t < EE) ? ei[EE + t] : (t - EE);
    rank[t] = atomicAdd(&deg[d], 1);
}

__global__ __launch_bounds__(1024) void csr_scan_kernel(
    int* __restrict__ deg, int* __restrict__ off)
{
    const int PER = 20;
    __shared__ int warpSums[32];
    int t    = threadIdx.x;
    int lane = t & 31, wid = t >> 5;
    int base = t * PER;

    int v[PER];
    int s = 0;
#pragma unroll
    for (int i = 0; i < PER; i++) {
        int idx = base + i;
        int x = (idx < NN) ? deg[idx] : 0;
        if (idx < NN) deg[idx] = 0;
        v[i] = s;
        s += x;
    }
    int incl = s;
#pragma unroll
    for (int o = 1; o < 32; o <<= 1) {
        int u = __shfl_up_sync(0xffffffffu, incl, o);
        if (lane >= o) incl += u;
    }
    if (lane == 31) warpSums[wid] = incl;
    __syncthreads();
    if (wid == 0) {
        int ws = warpSums[lane];
#pragma unroll
        for (int o = 1; o < 32; o <<= 1) {
            int u = __shfl_up_sync(0xffffffffu, ws, o);
            if (lane >= o) ws += u;
        }
        warpSums[lane] = ws;
    }
    __syncthreads();
    int warpPrefix  = (wid == 0) ? 0 : warpSums[wid - 1];
    int threadExcl  = warpPrefix + incl - s;
#pragma unroll
    for (int i = 0; i < PER; i++) {
        int idx = base + i;
        if (idx < NN) off[idx] = threadExcl + v[i];
    }
    if (t == 0) off[NN] = ETOT;
}

__global__ void csr_scatter_kernel(const int* __restrict__ ei,
                                   const int* __restrict__ off,
                                   const int* __restrict__ rank,
                                   int* __restrict__ csr_src)
{
    int t = blockIdx.x * blockDim.x + threadIdx.x;
    if (t >= ETOT) return;
    int s, d;
    if (t < EE) { s = ei[t]; d = ei[EE + t]; }
    else        { s = t - EE; d = s; }
    csr_src[off[d] + rank[t]] = s;
}

// ---------------------------------------------------------------------------
// GAT aggregation (H=4, C=64): ONE warp per dst; unroll-2; fp16 in AND out.
// ---------------------------------------------------------------------------
__global__ __launch_bounds__(256) void gat_gather4_kernel(
    const int* __restrict__ off, const int* __restrict__ csr_src,
    const __half* __restrict__ h,
    const float* __restrict__ as_, const float* __restrict__ ad_,
    const float* __restrict__ bias, __half* __restrict__ out,
    float* __restrict__ za, float* __restrict__ zd)
{
    int gt   = blockIdx.x * blockDim.x + threadIdx.x;
    if (za != nullptr && gt < NN * HEADS) { za[gt] = 0.f; zd[gt] = 0.f; }
    int d    = gt >> 5;
    int lane = gt & 31;
    if (d >= NN) return;

    const int head = lane >> 3;
    const uint4* hb = reinterpret_cast<const uint4*>(h);
    float adv = ad_[d * 4 + head];

    float acc[8];
#pragma unroll
    for (int k = 0; k < 8; k++) acc[k] = 0.f;
    float den = 0.f;

    int a   = off[d];
    int end = off[d + 1];
    for (; a + 1 < end; a += 2) {
        int s0 = csr_src[a];
        int s1 = csr_src[a + 1];
        float e0 = as_[s0 * 4 + head] + adv;
        float e1 = as_[s1 * 4 + head] + adv;
        uint4 v0 = hb[(size_t)s0 * 32 + lane];
        uint4 v1 = hb[(size_t)s1 * 32 + lane];
        e0 = e0 > 0.f ? e0 : 0.2f * e0;
        e1 = e1 > 0.f ? e1 : 0.2f * e1;
        float x0 = __expf(e0);
        float x1 = __expf(e1);
        {
            float2 f0 = __half22float2(*reinterpret_cast<__half2*>(&v0.x));
            float2 f1 = __half22float2(*reinterpret_cast<__half2*>(&v0.y));
            float2 f2 = __half22float2(*reinterpret_cast<__half2*>(&v0.z));
            float2 f3 = __half22float2(*reinterpret_cast<__half2*>(&v0.w));
            acc[0] += x0 * f0.x; acc[1] += x0 * f0.y;
            acc[2] += x0 * f1.x; acc[3] += x0 * f1.y;
            acc[4] += x0 * f2.x; acc[5] += x0 * f2.y;
            acc[6] += x0 * f3.x; acc[7] += x0 * f3.y;
        }
        {
            float2 f0 = __half22float2(*reinterpret_cast<__half2*>(&v1.x));
            float2 f1 = __half22float2(*reinterpret_cast<__half2*>(&v1.y));
            float2 f2 = __half22float2(*reinterpret_cast<__half2*>(&v1.z));
            float2 f3 = __half22float2(*reinterpret_cast<__half2*>(&v1.w));
            acc[0] += x1 * f0.x; acc[1] += x1 * f0.y;
            acc[2] += x1 * f1.x; acc[3] += x1 * f1.y;
            acc[4] += x1 * f2.x; acc[5] += x1 * f2.y;
            acc[6] += x1 * f3.x; acc[7] += x1 * f3.y;
        }
        den += x0 + x1;
    }
    if (a < end) {
        int s = csr_src[a];
        float e = as_[s * 4 + head] + adv;
        uint4 v = hb[(size_t)s * 32 + lane];
        e = e > 0.f ? e : 0.2f * e;
        float ex = __expf(e);
        float2 f0 = __half22float2(*reinterpret_cast<__half2*>(&v.x));
        float2 f1 = __half22float2(*reinterpret_cast<__half2*>(&v.y));
        float2 f2 = __half22float2(*reinterpret_cast<__half2*>(&v.z));
        float2 f3 = __half22float2(*reinterpret_cast<__half2*>(&v.w));
        acc[0] += ex * f0.x; acc[1] += ex * f0.y;
        acc[2] += ex * f1.x; acc[3] += ex * f1.y;
        acc[4] += ex * f2.x; acc[5] += ex * f2.y;
        acc[6] += ex * f3.x; acc[7] += ex * f3.y;
        den += ex;
    }

    float r = 1.f / (den + 1e-16f);
    float4 b0 = *reinterpret_cast<const float4*>(&bias[lane * 8]);
    float4 b1 = *reinterpret_cast<const float4*>(&bias[lane * 8 + 4]);
    float o[8];
    o[0] = acc[0] * r + b0.x; o[1] = acc[1] * r + b0.y;
    o[2] = acc[2] * r + b0.z; o[3] = acc[3] * r + b0.w;
    o[4] = acc[4] * r + b1.x; o[5] = acc[5] * r + b1.y;
    o[6] = acc[6] * r + b1.z; o[7] = acc[7] * r + b1.w;
#pragma unroll
    for (int k = 0; k < 8; k++) o[k] = o[k] > 0.f ? o[k] : expm1f(o[k]);

    uint4 ov;
    ov.x = h2_as_u32(__floats2half2_rn(o[0], o[1]));
    ov.y = h2_as_u32(__floats2half2_rn(o[2], o[3]));
    ov.z = h2_as_u32(__floats2half2_rn(o[4], o[5]));
    ov.w = h2_as_u32(__floats2half2_rn(o[6], o[7]));
    reinterpret_cast<uint4*>(out + (size_t)d * HC12)[lane] = ov;
}

// ---------------------------------------------------------------------------
// GAT aggregation (H=1, C=128): ONE warp per dst; fp32 out (final h).
// ---------------------------------------------------------------------------
__global__ __launch_bounds__(256) void gat_gather1_kernel(
    const int* __restrict__ off, const int* __restrict__ csr_src,
    const __half* __restrict__ h,
    const float* __restrict__ as_, const float* __restrict__ ad_,
    const float* __restrict__ bias, float* __restrict__ out)
{
    int gt   = blockIdx.x * blockDim.x + threadIdx.x;
    int d    = gt >> 5;
    int lane = gt & 31;
    if (d >= NN) return;

    const uint2* hb = reinterpret_cast<const uint2*>(h);
    float adv = ad_[d];
    float acc[4] = {0.f, 0.f, 0.f, 0.f};
    float den = 0.f;

    int a   = off[d];
    int end = off[d + 1];
    for (; a + 1 < end; a += 2) {
        int s0 = csr_src[a];
        int s1 = csr_src[a + 1];
        float e0 = as_[s0] + adv;
        float e1 = as_[s1] + adv;
        uint2 v0 = hb[(size_t)s0 * 32 + lane];
        uint2 v1 = hb[(size_t)s1 * 32 + lane];
        e0 = e0 > 0.f ? e0 : 0.2f * e0;
        e1 = e1 > 0.f ? e1 : 0.2f * e1;
        float x0 = __expf(e0);
        float x1 = __expf(e1);
        {
            float2 f0 = __half22float2(*reinterpret_cast<__half2*>(&v0.x));
            float2 f1 = __half22float2(*reinterpret_cast<__half2*>(&v0.y));
            acc[0] += x0 * f0.x; acc[1] += x0 * f0.y;
            acc[2] += x0 * f1.x; acc[3] += x0 * f1.y;
        }
        {
            float2 f0 = __half22float2(*reinterpret_cast<__half2*>(&v1.x));
            float2 f1 = __half22float2(*reinterpret_cast<__half2*>(&v1.y));
            acc[0] += x1 * f0.x; acc[1] += x1 * f0.y;
            acc[2] += x1 * f1.x; acc[3] += x1 * f1.y;
        }
        den += x0 + x1;
    }
    if (a < end) {
        int s = csr_src[a];
        float e = as_[s] + adv;
        uint2 v = hb[(size_t)s * 32 + lane];
        e = e > 0.f ? e : 0.2f * e;
        float ex = __expf(e);
        float2 f0 = __half22float2(*reinterpret_cast<__half2*>(&v.x));
        float2 f1 = __half22float2(*reinterpret_cast<__half2*>(&v.y));
        acc[0] += ex * f0.x; acc[1] += ex * f0.y;
        acc[2] += ex * f1.x; acc[3] += ex * f1.y;
        den += ex;
    }

    float r = 1.f / (den + 1e-16f);
    float4 b = *reinterpret_cast<const float4*>(&bias[lane * 4]);
    float4 o;
    o.x = acc[0] * r + b.x; o.y = acc[1] * r + b.y;
    o.z = acc[2] * r + b.z; o.w = acc[3] * r + b.w;
    reinterpret_cast<float4*>(out + (size_t)d * FOUT)[lane] = o;
}

// ---------------------------------------------------------------------------
// Segmented global mean pool (batch sorted)
// ---------------------------------------------------------------------------
__global__ __launch_bounds__(128) void pool_kernel(
    const float* __restrict__ h, const int* __restrict__ bat,
    float* __restrict__ out_emb)
{
    int g = blockIdx.x;
    int c = threadIdx.x;

    int lo = 0, hi = NN;
    while (lo < hi) { int m = (lo + hi) >> 1; if (bat[m] < g) lo = m + 1; else hi = m; }
    int start = lo;
    lo = 0; hi = NN;
    while (lo < hi) { int m = (lo + hi) >> 1; if (bat[m] < g + 1) lo = m + 1; else hi = m; }
    int end = lo;

    float s0 = 0.f, s1 = 0.f, s2 = 0.f, s3 = 0.f;
    int n = start;
    for (; n + 3 < end; n += 4) {
        s0 += h[(size_t)n * FOUT + c];
        s1 += h[(size_t)(n + 1) * FOUT + c];
        s2 += h[(size_t)(n + 2) * FOUT + c];
        s3 += h[(size_t)(n + 3) * FOUT + c];
    }
    for (; n < end; n++) s0 += h[(size_t)n * FOUT + c];
    float s = (s0 + s1) + (s2 + s3);
    out_emb[g * FOUT + c] = s / fmaxf((float)(end - start), 1.f);
}

// ---------------------------------------------------------------------------
// Launch
// ---------------------------------------------------------------------------
extern "C" void kernel_launch(void* const* d_in, const int* in_sizes, int n_in,
                              void* d_out, int out_size)
{
    const float* x   = (const float*)d_in[0];
    const int*   ei  = (const int*)d_in[1];
    const int*   bat = (const int*)d_in[2];
    const float* W1  = (const float*)d_in[3];
    const float* as1 = (const float*)d_in[4];
    const float* ad1 = (const float*)d_in[5];
    const float* b1  = (const float*)d_in[6];
    const float* W2  = (const float*)d_in[7];
    const float* as2 = (const float*)d_in[8];
    const float* ad2 = (const float*)d_in[9];
    const float* b2  = (const float*)d_in[10];
    const float* W3  = (const float*)d_in[11];
    const float* as3 = (const float*)d_in[12];
    const float* ad3 = (const float*)d_in[13];
    const float* b3  = (const float*)d_in[14];

    float* out     = (float*)d_out;
    float* out_emb = out;                 // [G, FOUT]
    float* out_h   = out + GG * FOUT;     // [N, FOUT]

    __half *h16, *b16, *x16, *w16;
    float *asA, *adA, *asB, *adB;
    int *deg, *off, *rank, *csr_src;
    cudaGetSymbolAddress((void**)&h16,  g_h16);
    cudaGetSymbolAddress((void**)&b16,  g_b16);
    cudaGetSymbolAddress((void**)&x16,  g_x16);
    cudaGetSymbolAddress((void**)&w16,  g_w16);
    cudaGetSymbolAddress((void**)&asA,  g_asA);
    cudaGetSymbolAddress((void**)&adA,  g_adA);
    cudaGetSymbolAddress((void**)&asB,  g_asB);
    cudaGetSymbolAddress((void**)&adB,  g_adB);
    cudaGetSymbolAddress((void**)&deg,  g_deg);
    cudaGetSymbolAddress((void**)&off,  g_off);
    cudaGetSymbolAddress((void**)&rank, g_rank);
    cudaGetSymbolAddress((void**)&csr_src, g_csr_src);

    __half* w16_1 = w16;
    __half* w16_2 = w16 + 32768;
    __half* w16_3 = w16 + 98304;

    static cudaStream_t sideStream = nullptr;
    static cudaEvent_t evFork = nullptr, evJoin = nullptr;
    if (sideStream == nullptr) {
        cudaStreamCreateWithFlags(&sideStream, cudaStreamNonBlocking);
        cudaEventCreateWithFlags(&evFork, cudaEventDisableTiming);
        cudaEventCreateWithFlags(&evJoin, cudaEventDisableTiming);
    }

    // --- fork: CSR build on side stream ---
    cudaEventRecord(evFork, 0);
    cudaStreamWaitEvent(sideStream, evFork, 0);
    csr_count_kernel<<<(ETOT + 255) / 256, 256, 0, sideStream>>>(ei, deg, rank);
    csr_scan_kernel<<<1, 1024, 0, sideStream>>>(deg, off);
    csr_scatter_kernel<<<(ETOT + 255) / 256, 256, 0, sideStream>>>(ei, off, rank, csr_src);
    cudaEventRecord(evJoin, sideStream);

    const int nby = (NN + 127) / 128;
    const int gatherGrid = (NN * 32 + 255) / 256;

    // --- main stream: cvt + layer-1 GEMM overlap with CSR ---
    cvt_kernel<<<(NN * FIN / 4 + 255) / 256, 256>>>(
        (const float4*)x, (uint2*)x16, (const float4*)W1, (const float4*)W2,
        (const float4*)W3, (uint2*)w16, asA, adA, asB, adB);
    gemm_tc_kernel<<<dim3(HC12 / 64, nby), 256>>>(x16, w16_1, h16, NN, FIN, HC12,
                                                  as1, ad1, asA, adA, HEADS, HID);

    // --- join: gathers need the CSR ---
    cudaStreamWaitEvent(0, evJoin, 0);

    gat_gather4_kernel<<<gatherGrid, 256>>>(off, csr_src, h16, asA, adA, b1, b16,
                                            nullptr, nullptr);

    // --- Layer 2 ---
    gemm_tc_kernel<<<dim3(HC12 / 64, nby), 256>>>(b16, w16_2, h16, NN, HC12, HC12,
                                                  as2, ad2, asB, adB, HEADS, HID);
    gat_gather4_kernel<<<gatherGrid, 256>>>(off, csr_src, h16, asB, adB, b2, b16,
                                            asA, adA);

    // --- Layer 3 ---
    gemm_tc_kernel<<<dim3(FOUT / 64, nby), 256>>>(b16, w16_3, h16, NN, HC12, FOUT,
                                                  as3, ad3, asA, adA, 1, FOUT);
    gat_gather1_kernel<<<gatherGrid, 256>>>(off, csr_src, h16, asA, adA, b3, out_h);

    // --- segmented global mean pool ---
    pool_kernel<<<GG, 128>>>(out_h, bat, out_emb);
}